// round 7
// baseline (speedup 1.0000x reference)
#include <cuda_runtime.h>
#include <cuda_bf16.h>
#include <math.h>
#include <stdint.h>

#define BB 16
#define SS 128
#define VV 40000
#define DD 768
#define HH 12
#define HD 64
#define FF 3072
#define LL 12

typedef __nv_bfloat16 bf16;

// ---------------- fp32 scratch ----------------
__device__ float g_h   [BB*SS*DD];
__device__ float g_qkv [BB*SS*3*DD];
__device__ float g_proj[BB*SS*DD];
__device__ float g_ff2 [BB*SS*DD];
__device__ float g_bqkv[LL*3*DD];

// ---------------- bf16 split weights [N][K] ----------------
__device__ bf16 s_wqkv[2][LL*3*DD*DD];
__device__ bf16 s_wo  [2][LL*DD*DD];
__device__ bf16 s_w1  [2][LL*DD*FF];
__device__ bf16 s_w2  [2][LL*FF*DD];
__device__ bf16 s_wout[2][VV*DD];
__device__ bf16 s_actA[2][BB*SS*FF];
__device__ bf16 s_actB[2][BB*SS*FF];

// ======================= helpers =======================
__device__ __forceinline__ uint32_t smem_u32(const void* p) {
    uint32_t a;
    asm("{ .reg .u64 t; cvta.to.shared.u64 t, %1; cvt.u32.u64 %0, t; }" : "=r"(a) : "l"(p));
    return a;
}
__device__ __forceinline__ void cp16(uint32_t dst, const void* src) {
    asm volatile("cp.async.cg.shared.global [%0], [%1], 16;" :: "r"(dst), "l"(src) : "memory");
}
__device__ __forceinline__ void zero16(uint32_t dst) {
    asm volatile("st.shared.v4.b32 [%0], {%1,%1,%1,%1};" :: "r"(dst), "r"(0u) : "memory");
}
__device__ __forceinline__ void cp_commit() {
    asm volatile("cp.async.commit_group;" ::: "memory");
}
__device__ __forceinline__ void ldm4(uint32_t addr, uint32_t* r) {
    asm volatile("ldmatrix.sync.aligned.m8n8.x4.shared.b16 {%0,%1,%2,%3}, [%4];"
                 : "=r"(r[0]), "=r"(r[1]), "=r"(r[2]), "=r"(r[3]) : "r"(addr));
}
__device__ __forceinline__ void mma16816(float* d, const uint32_t* a, uint32_t b0, uint32_t b1) {
    asm volatile(
        "mma.sync.aligned.m16n8k16.row.col.f32.bf16.bf16.f32 "
        "{%0,%1,%2,%3}, {%4,%5,%6,%7}, {%8,%9}, {%0,%1,%2,%3};"
        : "+f"(d[0]), "+f"(d[1]), "+f"(d[2]), "+f"(d[3])
        : "r"(a[0]), "r"(a[1]), "r"(a[2]), "r"(a[3]), "r"(b0), "r"(b1));
}
__device__ __forceinline__ void split_bf16(float v, bf16& h, bf16& l) {
    h = __float2bfloat16(v);
    l = __float2bfloat16(v - __bfloat162float(h));
}

#define TROW 80

// ======================= small kernels =======================
__global__ void embed_kernel(const int* __restrict__ x,
                             const float* __restrict__ bpe,
                             const float* __restrict__ pe,
                             bf16* __restrict__ ah, bf16* __restrict__ al) {
    int idx = blockIdx.x * blockDim.x + threadIdx.x;
    if (idx >= BB*SS*DD) return;
    int d  = idx % DD;
    int bs = idx / DD;
    int s  = bs % SS;
    int tok = x[bs];
    float v = bpe[(long)tok*DD + d] + pe[s*DD + d];
    g_h[idx] = v;
    bf16 h, l; split_bf16(v, h, l);
    ah[idx] = h; al[idx] = l;
}

__global__ void concat_bias(const float* __restrict__ bq, const float* __restrict__ bk,
                            const float* __restrict__ bv) {
    int idx = blockIdx.x * blockDim.x + threadIdx.x;
    if (idx >= LL*3*DD) return;
    int l = idx / (3*DD), n = idx % (3*DD);
    float v;
    if (n < DD)          v = bq[l*DD + n];
    else if (n < 2*DD)   v = bk[l*DD + n - DD];
    else                 v = bv[l*DD + n - 2*DD];
    g_bqkv[idx] = v;
}

__global__ void conv_transpose(const float* __restrict__ src, bf16* __restrict__ dhi,
                               bf16* __restrict__ dlo, int R, int C,
                               long srcZ, int Z2, long dstZ1, long dstZ2) {
    __shared__ float t[32][33];
    int c0 = blockIdx.x * 32, r0 = blockIdx.y * 32;
    long zs = (long)blockIdx.z * srcZ;
    long zd = (long)(blockIdx.z / Z2) * dstZ1 + (long)(blockIdx.z % Z2) * dstZ2;
    int tx = threadIdx.x, ty = threadIdx.y;   // (16,16)
    #pragma unroll
    for (int i = 0; i < 2; i++) {
        int r = ty + i * 16;
        float2 v = *reinterpret_cast<const float2*>(&src[zs + (long)(r0 + r) * C + c0 + tx*2]);
        t[tx*2][r] = v.x;
        t[tx*2+1][r] = v.y;
    }
    __syncthreads();
    #pragma unroll
    for (int i = 0; i < 2; i++) {
        int cc = ty + i * 16;
        float a0 = t[cc][tx*2], a1 = t[cc][tx*2+1];
        bf16 h0, l0, h1, l1;
        split_bf16(a0, h0, l0);
        split_bf16(a1, h1, l1);
        long o = zd + (long)(c0 + cc) * R + r0 + tx*2;
        *reinterpret_cast<__nv_bfloat162*>(&dhi[o]) = __nv_bfloat162(h0, h1);
        *reinterpret_cast<__nv_bfloat162*>(&dlo[o]) = __nv_bfloat162(l0, l1);
    }
}

// ======================= gemm128t: 128x128 tile, 128 thr, warp 64x64 =======================
// stage: AH@0, AL@10240, BH@20480, BL@30720 ; stage=40960, 2 stages = 81920
#define T1_AH 0
#define T1_AL 10240
#define T1_BH 20480
#define T1_BL 30720
#define T1_STAGE 40960
#define T1_SMEM (2*T1_STAGE)

__device__ __forceinline__ void load128t(
    uint32_t bb, const bf16* __restrict__ Ah, const bf16* __restrict__ Al,
    const bf16* __restrict__ Bh, const bf16* __restrict__ Bl,
    int m0, int n0, int N, int K, int c, int tid)
{
    int k0 = c << 5;
    #pragma unroll
    for (int i = 0; i < 4; i++) {
        int ci = tid + i * 128;              // 0..511 : 128 rows x 4 quads
        int row = ci >> 2, kq = ci & 3;
        uint32_t doff = (uint32_t)(row * TROW + kq * 16);
        long aoff = (long)(m0 + row) * K + k0 + kq * 8;
        cp16(bb + T1_AH + doff, Ah + aoff);
        cp16(bb + T1_AL + doff, Al + aoff);
        int nr = n0 + row;
        if (nr < N) {
            long boff = (long)nr * K + k0 + kq * 8;
            cp16(bb + T1_BH + doff, Bh + boff);
            cp16(bb + T1_BL + doff, Bl + boff);
        } else {
            zero16(bb + T1_BH + doff);
            zero16(bb + T1_BL + doff);
        }
    }
}

template<int OUT>
__global__ __launch_bounds__(128, 2) void gemm128t(
    const bf16* __restrict__ Ah, const bf16* __restrict__ Al,
    const bf16* __restrict__ Bh, const bf16* __restrict__ Bl,
    const float* __restrict__ bias, float* __restrict__ C,
    bf16* __restrict__ Oh, bf16* __restrict__ Ol,
    int N, int K)
{
    extern __shared__ char smem[];
    const uint32_t base = smem_u32(smem);
    const int tid  = threadIdx.x;
    const int lane = tid & 31;
    const int w    = tid >> 5;       // 0..3
    const int wm   = w & 1;          // 2 m-slots of 64
    const int wn   = w >> 1;         // 2 n-slots of 64
    const int m0 = blockIdx.x * 128, n0 = blockIdx.y * 128;
    const int nCh = K >> 5;

    float acc[4][8][4];
    #pragma unroll
    for (int i = 0; i < 4; i++)
        #pragma unroll
        for (int j = 0; j < 8; j++)
            #pragma unroll
            for (int q = 0; q < 4; q++) acc[i][j][q] = 0.f;

    const uint32_t a_loff = (uint32_t)((lane & 15) * TROW + ((lane >> 4) << 3) * 2);
    const uint32_t b_loff = (uint32_t)((((lane & 7) + ((lane & 16) ? 8 : 0)) * TROW) +
                                       ((lane & 8) ? 16 : 0));

    load128t(base, Ah, Al, Bh, Bl, m0, n0, N, K, 0, tid);
    cp_commit();

    for (int c = 0; c < nCh; c++) {
        if (c + 1 < nCh) {
            load128t(base + (uint32_t)((c + 1) & 1) * T1_STAGE,
                     Ah, Al, Bh, Bl, m0, n0, N, K, c + 1, tid);
            cp_commit();
            asm volatile("cp.async.wait_group 1;" ::: "memory");
        } else {
            asm volatile("cp.async.wait_group 0;" ::: "memory");
        }
        __syncthreads();

        uint32_t bb = base + (uint32_t)(c & 1) * T1_STAGE;
        uint32_t aH = bb + T1_AH + (uint32_t)(wm * 64) * TROW;
        uint32_t aL = bb + T1_AL + (uint32_t)(wm * 64) * TROW;
        uint32_t bH = bb + T1_BH + (uint32_t)(wn * 64) * TROW;
        uint32_t bL = bb + T1_BL + (uint32_t)(wn * 64) * TROW;

        #pragma unroll
        for (int ks = 0; ks < 2; ks++) {
            const uint32_t koff = (uint32_t)(ks * 32);
            uint32_t ah[4][4], al[4][4];
            #pragma unroll
            for (int mi = 0; mi < 4; mi++) {
                ldm4(aH + (uint32_t)(mi * 16) * TROW + a_loff + koff, ah[mi]);
                ldm4(aL + (uint32_t)(mi * 16) * TROW + a_loff + koff, al[mi]);
            }
            #pragma unroll
            for (int g = 0; g < 4; g++) {            // 4 groups of 16 cols
                uint32_t bh[4], bl[4];
                ldm4(bH + (uint32_t)(g * 16) * TROW + b_loff + koff, bh);
                ldm4(bL + (uint32_t)(g * 16) * TROW + b_loff + koff, bl);
                #pragma unroll
                for (int mi = 0; mi < 4; mi++) {
                    float* a0 = acc[mi][g * 2];
                    float* a1 = acc[mi][g * 2 + 1];
                    mma16816(a0, ah[mi], bh[0], bh[1]);
                    mma16816(a0, ah[mi], bl[0], bl[1]);
                    mma16816(a0, al[mi], bh[0], bh[1]);
                    mma16816(a1, ah[mi], bh[2], bh[3]);
                    mma16816(a1, ah[mi], bl[2], bl[3]);
                    mma16816(a1, al[mi], bh[2], bh[3]);
                }
            }
        }
        __syncthreads();
    }

    // epilogue
    #pragma unroll
    for (int mi = 0; mi < 4; mi++) {
        int row = m0 + wm * 64 + mi * 16 + (lane >> 2);
        #pragma unroll
        for (int ni = 0; ni < 8; ni++) {
            int col = n0 + wn * 64 + ni * 8 + ((lane & 3) << 1);
            if (col < N) {
                float bx = bias[col], by = bias[col + 1];
                float v00 = acc[mi][ni][0] + bx, v01 = acc[mi][ni][1] + by;
                float v10 = acc[mi][ni][2] + bx, v11 = acc[mi][ni][3] + by;
                if (OUT == 0) {
                    *reinterpret_cast<float2*>(C + (long)row * N + col)       = make_float2(v00, v01);
                    *reinterpret_cast<float2*>(C + (long)(row + 8) * N + col) = make_float2(v10, v11);
                } else {
                    bf16 h0,l0,h1,l1,h2,l2,h3,l3;
                    split_bf16(v00, h0, l0); split_bf16(v01, h1, l1);
                    split_bf16(v10, h2, l2); split_bf16(v11, h3, l3);
                    *reinterpret_cast<__nv_bfloat162*>(Oh + (long)row * N + col)       = __nv_bfloat162(h0, h1);
                    *reinterpret_cast<__nv_bfloat162*>(Ol + (long)row * N + col)       = __nv_bfloat162(l0, l1);
                    *reinterpret_cast<__nv_bfloat162*>(Oh + (long)(row + 8) * N + col) = __nv_bfloat162(h2, h3);
                    *reinterpret_cast<__nv_bfloat162*>(Ol + (long)(row + 8) * N + col) = __nv_bfloat162(l2, l3);
                }
            }
        }
    }
}

// ======================= gemm_hmma64 (proj / FF2) =======================
__device__ __forceinline__ void load_chunk64(
    uint32_t base, const bf16* __restrict__ Ah, const bf16* __restrict__ Al,
    const bf16* __restrict__ Bh, const bf16* __restrict__ Bl,
    int m0, int n0, int N, int K, int c, int tid)
{
    const uint32_t A_BYTES = 64 * TROW;
    const uint32_t BUF = (2 * 64 + 256) * TROW;
    uint32_t bb = base + (uint32_t)(c & 1) * BUF;
    int k0 = c << 5;
    {
        int row = tid >> 2, kq = tid & 3;
        if (row < 64) {
            uint32_t doff = (uint32_t)(row * TROW + kq * 16);
            long aoff = (long)(m0 + row) * K + k0 + kq * 8;
            cp16(bb + doff, Ah + aoff);
            cp16(bb + A_BYTES + doff, Al + aoff);
        }
    }
    #pragma unroll
    for (int i = 0; i < 2; i++) {
        int ci  = tid + i * 256;
        int row = ci >> 2, kq = ci & 3;
        uint32_t doff = (uint32_t)(row * TROW + kq * 16);
        int nr = n0 + row;
        if (nr < N) {
            long boff = (long)nr * K + k0 + kq * 8;
            cp16(bb + 2*A_BYTES + doff, Bh + boff);
            cp16(bb + 2*A_BYTES + 128*TROW + doff, Bl + boff);
        } else {
            zero16(bb + 2*A_BYTES + doff);
            zero16(bb + 2*A_BYTES + 128*TROW + doff);
        }
    }
}

__global__ __launch_bounds__(256, 2) void gemm_hmma64(
    const bf16* __restrict__ Ah, const bf16* __restrict__ Al,
    const bf16* __restrict__ Bh, const bf16* __restrict__ Bl,
    const float* __restrict__ bias, float* __restrict__ C,
    int N, int K)
{
    const uint32_t A_BYTES = 64 * TROW;
    const uint32_t BUF = (2 * 64 + 256) * TROW;
    extern __shared__ char smem[];
    const uint32_t base = smem_u32(smem);
    const int tid  = threadIdx.x;
    const int lane = tid & 31;
    const int w    = tid >> 5;
    const int wm   = w & 1;
    const int wn   = w >> 1;
    const int m0 = blockIdx.x * 64, n0 = blockIdx.y * 128;
    const int nCh = K >> 5;

    float acc[2][4][4];
    #pragma unroll
    for (int i = 0; i < 2; i++)
        #pragma unroll
        for (int j = 0; j < 4; j++)
            #pragma unroll
            for (int q = 0; q < 4; q++) acc[i][j][q] = 0.f;

    const uint32_t a_loff = (uint32_t)((lane & 15) * TROW + ((lane >> 4) << 3) * 2);
    const uint32_t b_loff = (uint32_t)((((lane & 7) + ((lane & 16) ? 8 : 0)) * TROW) +
                                       ((lane & 8) ? 16 : 0));

    load_chunk64(base, Ah, Al, Bh, Bl, m0, n0, N, K, 0, tid);
    cp_commit();

    for (int c = 0; c < nCh; c++) {
        if (c + 1 < nCh) {
            load_chunk64(base, Ah, Al, Bh, Bl, m0, n0, N, K, c + 1, tid);
            cp_commit();
            asm volatile("cp.async.wait_group 1;" ::: "memory");
        } else {
            asm volatile("cp.async.wait_group 0;" ::: "memory");
        }
        __syncthreads();

        uint32_t bb = base + (uint32_t)(c & 1) * BUF;
        uint32_t aH = bb + (uint32_t)(wm * 32) * TROW;
        uint32_t aL = aH + A_BYTES;
        uint32_t bH = bb + 2 * A_BYTES + (uint32_t)(wn * 32) * TROW;
        uint32_t bL = bH + 128 * TROW;

        #pragma unroll
        for (int ks = 0; ks < 2; ks++) {
            const uint32_t koff = (uint32_t)(ks * 32);
            uint32_t bh[2][4], bl[2][4];
            #pragma unroll
            for (int g = 0; g < 2; g++) {
                ldm4(bH + (uint32_t)(g * 16) * TROW + b_loff + koff, bh[g]);
                ldm4(bL + (uint32_t)(g * 16) * TROW + b_loff + koff, bl[g]);
            }
            #pragma unroll
            for (int mi = 0; mi < 2; mi++) {
                uint32_t ah[4], al[4];
                ldm4(aH + (uint32_t)(mi * 16) * TROW + a_loff + koff, ah);
                ldm4(aL + (uint32_t)(mi * 16) * TROW + a_loff + koff, al);
                #pragma unroll
                for (int ni = 0; ni < 4; ni++) {
                    const int g = ni >> 1, o = (ni & 1) * 2;
                    mma16816(acc[mi][ni], ah, bh[g][o], bh[g][o + 1]);
                    mma16816(acc[mi][ni], ah, bl[g][o], bl[g][o + 1]);
                    mma16816(acc[mi][ni], al, bh[g][o], bh[g][o + 1]);
                }
            }
        }
        __syncthreads();
    }

    #pragma unroll
    for (int mi = 0; mi < 2; mi++) {
        int row = m0 + wm * 32 + mi * 16 + (lane >> 2);
        #pragma unroll
        for (int ni = 0; ni < 4; ni++) {
            int col = n0 + wn * 32 + ni * 8 + ((lane & 3) << 1);
            if (col < N) {
                float bx = bias[col], by = bias[col + 1];
                *reinterpret_cast<float2*>(C + (long)row * N + col) =
                    make_float2(acc[mi][ni][0] + bx, acc[mi][ni][1] + by);
                *reinterpret_cast<float2*>(C + (long)(row + 8) * N + col) =
                    make_float2(acc[mi][ni][2] + bx, acc[mi][ni][3] + by);
            }
        }
    }
}

// ======================= attention =======================
__global__ __launch_bounds__(128) void attn_kernel(const int* __restrict__ ignore,
                                                   bf16* __restrict__ oh,
                                                   bf16* __restrict__ ol) {
    const int qi = blockIdx.x & (SS - 1);
    const int h  = (blockIdx.x >> 7) % HH;
    const int b  = blockIdx.x / (SS * HH);
    const int t  = threadIdx.x;
    const int QW = 3 * DD;

    __shared__ float qrow[HD];
    __shared__ float p[SS];
    __shared__ float red[SS];

    const float* qptr = g_qkv + ((long)(b * SS + qi) * QW + h * HD);
    if (t < HD) qrow[t] = qptr[t];
    __syncthreads();

    const bool allowed = (t <= qi) && (ignore[b * SS + t] == 0 || t == qi);
    float score = -INFINITY;
    if (allowed) {
        const float* kptr = g_qkv + ((long)(b * SS + t) * QW + DD + h * HD);
        float s = 0.f;
        #pragma unroll
        for (int e = 0; e < HD; e++) s += qrow[e] * kptr[e];
        score = s * 0.125f;
    }
    red[t] = score; __syncthreads();
    for (int off = 64; off > 0; off >>= 1) {
        if (t < off) red[t] = fmaxf(red[t], red[t + off]);
        __syncthreads();
    }
    const float mx = red[0];
    __syncthreads();
    const float e = allowed ? expf(score - mx) : 0.f;
    p[t] = e; red[t] = e; __syncthreads();
    for (int off = 64; off > 0; off >>= 1) {
        if (t < off) red[t] += red[t + off];
        __syncthreads();
    }
    const float inv = 1.f / red[0];
    if (t < HD) {
        const float* vbase = g_qkv + ((long)b * SS * QW + 2 * DD + h * HD + t);
        float o = 0.f;
        #pragma unroll 4
        for (int k = 0; k < SS; k++) o += p[k] * vbase[(long)k * QW];
        o *= inv;
        long oidx = (long)(b * SS + qi) * DD + h * HD + t;
        bf16 hh, ll; split_bf16(o, hh, ll);
        oh[oidx] = hh; ol[oidx] = ll;
    }
}

// ======================= residual (+GELU) + LayerNorm + split =======================
__global__ __launch_bounds__(256) void add_ln_kernel(
    const float* __restrict__ res_in,
    const float* __restrict__ w, const float* __restrict__ bvec,
    bf16* __restrict__ ah, bf16* __restrict__ al,
    int dogelu) {
    const int row = blockIdx.x;
    const int t = threadIdx.x;
    __shared__ float red[256];

    float vals[3];
    float sum = 0.f;
    #pragma unroll
    for (int i = 0; i < 3; i++) {
        int d = t + i * 256;
        float r = res_in[(long)row * DD + d];
        if (dogelu) r = 0.5f * r * (1.f + erff(r * 0.70710678118f));
        float v = g_h[(long)row * DD + d] + r;
        vals[i] = v;
        sum += v;
    }
    red[t] = sum; __syncthreads();
    for (int off = 128; off > 0; off >>= 1) {
        if (t < off) red[t] += red[t + off];
        __syncthreads();
    }
    const float mean = red[0] * (1.f / DD);
    __syncthreads();
    float vs = 0.f;
    #pragma unroll
    for (int i = 0; i < 3; i++) { float dv = vals[i] - mean; vs += dv * dv; }
    red[t] = vs; __syncthreads();
    for (int off = 128; off > 0; off >>= 1) {
        if (t < off) red[t] += red[t + off];
        __syncthreads();
    }
    const float rstd = rsqrtf(red[0] * (1.f / DD) + 1e-5f);
    #pragma unroll
    for (int i = 0; i < 3; i++) {
        int d = t + i * 256;
        float v = (vals[i] - mean) * rstd * w[d] + bvec[d];
        g_h[(long)row * DD + d] = v;
        bf16 hh, ll; split_bf16(v, hh, ll);
        ah[(long)row * DD + d] = hh;
        al[(long)row * DD + d] = ll;
    }
}

// ======================= host orchestration =======================
extern "C" void kernel_launch(void* const* d_in, const int* in_sizes, int n_in,
                              void* d_out, int out_size) {
    const int*   x    = (const int*)  d_in[0];
    const int*   ign  = (const int*)  d_in[1];
    const float* bpe  = (const float*)d_in[2];
    const float* pe   = (const float*)d_in[3];
    const float* Wq   = (const float*)d_in[4];
    const float* bq   = (const float*)d_in[5];
    const float* Wk   = (const float*)d_in[6];
    const float* bk   = (const float*)d_in[7];
    const float* Wv   = (const float*)d_in[8];
    const float* bv   = (const float*)d_in[9];
    const float* Wo   = (const float*)d_in[10];
    const float* bo   = (const float*)d_in[11];
    const float* W1   = (const float*)d_in[12];
    const float* b1   = (const float*)d_in[13];
    const float* W2   = (const float*)d_in[14];
    const float* b2   = (const float*)d_in[15];
    const float* ln1w = (const float*)d_in[16];
    const float* ln1b = (const float*)d_in[17];
    const float* ln2w = (const float*)d_in[18];
    const float* ln2b = (const float*)d_in[19];
    const float* Wout = (const float*)d_in[20];
    const float* bout = (const float*)d_in[21];
    float* out = (float*)d_out;

    float *gh, *gqkv, *gproj, *gff2, *gbqkv;
    cudaGetSymbolAddress((void**)&gh,    g_h);
    cudaGetSymbolAddress((void**)&gqkv,  g_qkv);
    cudaGetSymbolAddress((void**)&gproj, g_proj);
    cudaGetSymbolAddress((void**)&gff2,  g_ff2);
    cudaGetSymbolAddress((void**)&gbqkv, g_bqkv);

    bf16 *wqkv_h, *wo_h, *w1_h, *w2_h, *wout_h, *actA_h, *actB_h;
    bf16 *wqkv_l, *wo_l, *w1_l, *w2_l, *wout_l, *actA_l, *actB_l;
    void* p;
    cudaGetSymbolAddress(&p, s_wqkv); wqkv_h = (bf16*)p; wqkv_l = wqkv_h + (long)LL*3*DD*DD;
    cudaGetSymbolAddress(&p, s_wo);   wo_h = (bf16*)p;   wo_l   = wo_h   + (long)LL*DD*DD;
    cudaGetSymbolAddress(&p, s_w1);   w1_h = (bf16*)p;   w1_l   = w1_h   + (long)LL*DD*FF;
    cudaGetSymbolAddress(&p, s_w2);   w2_h = (bf16*)p;   w2_l   = w2_h   + (long)LL*FF*DD;
    cudaGetSymbolAddress(&p, s_wout); wout_h = (bf16*)p; wout_l = wout_h + (long)VV*DD;
    cudaGetSymbolAddress(&p, s_actA); actA_h = (bf16*)p; actA_l = actA_h + (long)BB*SS*FF;
    cudaGetSymbolAddress(&p, s_actB); actB_h = (bf16*)p; actB_l = actB_h + (long)BB*SS*FF;

    const int SM64 = (2*64 + 256) * TROW * 2;    // 61440
    cudaFuncSetAttribute(gemm128t<0>, cudaFuncAttributeMaxDynamicSharedMemorySize, T1_SMEM);
    cudaFuncSetAttribute(gemm128t<1>, cudaFuncAttributeMaxDynamicSharedMemorySize, T1_SMEM);
    cudaFuncSetAttribute(gemm_hmma64, cudaFuncAttributeMaxDynamicSharedMemorySize, SM64);

    const int M = BB * SS;  // 2048
    dim3 tb16(16, 16);

    // ---- weight conversion ----
    conv_transpose<<<dim3(HD/32, DD/32, LL*HH), tb16>>>(Wq, wqkv_h + 0L*DD*DD, wqkv_l + 0L*DD*DD,
        DD, HD, (long)DD*HD, HH, (long)3*DD*DD, (long)HD*DD);
    conv_transpose<<<dim3(HD/32, DD/32, LL*HH), tb16>>>(Wk, wqkv_h + 1L*DD*DD, wqkv_l + 1L*DD*DD,
        DD, HD, (long)DD*HD, HH, (long)3*DD*DD, (long)HD*DD);
    conv_transpose<<<dim3(HD/32, DD/32, LL*HH), tb16>>>(Wv, wqkv_h + 2L*DD*DD, wqkv_l + 2L*DD*DD,
        DD, HD, (long)DD*HD, HH, (long)3*DD*DD, (long)HD*DD);
    conv_transpose<<<dim3(DD/32, DD/32, LL), tb16>>>(Wo, wo_h, wo_l,
        DD, DD, (long)DD*DD, 1, (long)DD*DD, 0);
    conv_transpose<<<dim3(FF/32, DD/32, LL), tb16>>>(W1, w1_h, w1_l,
        DD, FF, (long)DD*FF, 1, (long)DD*FF, 0);
    conv_transpose<<<dim3(DD/32, FF/32, LL), tb16>>>(W2, w2_h, w2_l,
        FF, DD, (long)FF*DD, 1, (long)FF*DD, 0);
    conv_transpose<<<dim3(VV/32, DD/32, 1), tb16>>>(Wout, wout_h, wout_l,
        DD, VV, 0, 1, 0, 0);
    concat_bias<<<(LL*3*DD + 255)/256, 256>>>(bq, bk, bv);

    embed_kernel<<<(BB*SS*DD + 255)/256, 256>>>(x, bpe, pe, actA_h, actA_l);

    for (int l = 0; l < LL; l++) {
        gemm128t<0><<<dim3(M/128, (3*DD)/128), 128, T1_SMEM>>>(actA_h, actA_l,
            wqkv_h + (long)l*3*DD*DD, wqkv_l + (long)l*3*DD*DD,
            gbqkv + (long)l*3*DD, gqkv, nullptr, nullptr, 3*DD, DD);

        attn_kernel<<<BB*HH*SS, 128>>>(ign, actB_h, actB_l);

        gemm_hmma64<<<dim3(M/64, DD/128), 256, SM64>>>(actB_h, actB_l,
            wo_h + (long)l*DD*DD, wo_l + (long)l*DD*DD,
            bo + (long)l*DD, gproj, DD, DD);
        add_ln_kernel<<<M, 256>>>(gproj, ln1w + (long)l*DD, ln1b + (long)l*DD,
                                  actA_h, actA_l, 0);

        gemm128t<1><<<dim3(M/128, FF/128), 128, T1_SMEM>>>(actA_h, actA_l,
            w1_h + (long)l*DD*FF, w1_l + (long)l*DD*FF,
            b1 + (long)l*FF, nullptr, actB_h, actB_l, FF, DD);
        gemm_hmma64<<<dim3(M/64, DD/128), 256, SM64>>>(actB_h, actB_l,
            w2_h + (long)l*FF*DD, w2_l + (long)l*FF*DD,
            b2 + (long)l*DD, gff2, DD, FF);
        add_ln_kernel<<<M, 256>>>(gff2, ln2w + (long)l*DD, ln2b + (long)l*DD,
                                  actA_h, actA_l, 1);
    }

    gemm128t<0><<<dim3(M/128, (VV + 127)/128), 128, T1_SMEM>>>(actA_h, actA_l,
        wout_h, wout_l, bout, out, nullptr, nullptr, VV, DD);
}

// round 9
// speedup vs baseline: 1.4174x; 1.4174x over previous
#include <cuda_runtime.h>
#include <cuda_bf16.h>
#include <math.h>
#include <stdint.h>

#define BB 16
#define SS 128
#define VV 40000
#define DD 768
#define HH 12
#define HD 64
#define FF 3072
#define LL 12

typedef __nv_bfloat16 bf16;

// ---------------- fp32 scratch ----------------
__device__ float g_h   [BB*SS*DD];
__device__ float g_qkv [BB*SS*3*DD];
__device__ float g_proj[BB*SS*DD];
__device__ float g_ff2 [BB*SS*DD];
__device__ float g_bqkv[LL*3*DD];

// ---------------- bf16 split weights [N][K] ----------------
__device__ bf16 s_wqkv[2][LL*3*DD*DD];
__device__ bf16 s_wo  [2][LL*DD*DD];
__device__ bf16 s_w1  [2][LL*DD*FF];
__device__ bf16 s_w2  [2][LL*FF*DD];
__device__ bf16 s_wout[2][VV*DD];
__device__ bf16 s_actA[2][BB*SS*FF];
__device__ bf16 s_actB[2][BB*SS*FF];

// ======================= helpers =======================
__device__ __forceinline__ uint32_t smem_u32(const void* p) {
    uint32_t a;
    asm("{ .reg .u64 t; cvta.to.shared.u64 t, %1; cvt.u32.u64 %0, t; }" : "=r"(a) : "l"(p));
    return a;
}
__device__ __forceinline__ void cp16(uint32_t dst, const void* src) {
    asm volatile("cp.async.cg.shared.global [%0], [%1], 16;" :: "r"(dst), "l"(src) : "memory");
}
__device__ __forceinline__ void zero16(uint32_t dst) {
    asm volatile("st.shared.v4.b32 [%0], {%1,%1,%1,%1};" :: "r"(dst), "r"(0u) : "memory");
}
__device__ __forceinline__ void cp_commit() {
    asm volatile("cp.async.commit_group;" ::: "memory");
}
__device__ __forceinline__ void ldm4(uint32_t addr, uint32_t* r) {
    asm volatile("ldmatrix.sync.aligned.m8n8.x4.shared.b16 {%0,%1,%2,%3}, [%4];"
                 : "=r"(r[0]), "=r"(r[1]), "=r"(r[2]), "=r"(r[3]) : "r"(addr));
}
__device__ __forceinline__ void mma16816(float* d, const uint32_t* a, uint32_t b0, uint32_t b1) {
    asm volatile(
        "mma.sync.aligned.m16n8k16.row.col.f32.bf16.bf16.f32 "
        "{%0,%1,%2,%3}, {%4,%5,%6,%7}, {%8,%9}, {%0,%1,%2,%3};"
        : "+f"(d[0]), "+f"(d[1]), "+f"(d[2]), "+f"(d[3])
        : "r"(a[0]), "r"(a[1]), "r"(a[2]), "r"(a[3]), "r"(b0), "r"(b1));
}
__device__ __forceinline__ void split_bf16(float v, bf16& h, bf16& l) {
    h = __float2bfloat16(v);
    l = __float2bfloat16(v - __bfloat162float(h));
}

#define TROW 80

// ======================= small kernels =======================
__global__ void embed_kernel(const int* __restrict__ x,
                             const float* __restrict__ bpe,
                             const float* __restrict__ pe,
                             bf16* __restrict__ ah, bf16* __restrict__ al) {
    int idx = blockIdx.x * blockDim.x + threadIdx.x;
    if (idx >= BB*SS*DD) return;
    int d  = idx % DD;
    int bs = idx / DD;
    int s  = bs % SS;
    int tok = x[bs];
    float v = bpe[(long)tok*DD + d] + pe[s*DD + d];
    g_h[idx] = v;
    bf16 h, l; split_bf16(v, h, l);
    ah[idx] = h; al[idx] = l;
}

__global__ void concat_bias(const float* __restrict__ bq, const float* __restrict__ bk,
                            const float* __restrict__ bv) {
    int idx = blockIdx.x * blockDim.x + threadIdx.x;
    if (idx >= LL*3*DD) return;
    int l = idx / (3*DD), n = idx % (3*DD);
    float v;
    if (n < DD)          v = bq[l*DD + n];
    else if (n < 2*DD)   v = bk[l*DD + n - DD];
    else                 v = bv[l*DD + n - 2*DD];
    g_bqkv[idx] = v;
}

__global__ void conv_transpose(const float* __restrict__ src, bf16* __restrict__ dhi,
                               bf16* __restrict__ dlo, int R, int C,
                               long srcZ, int Z2, long dstZ1, long dstZ2) {
    __shared__ float t[32][33];
    int c0 = blockIdx.x * 32, r0 = blockIdx.y * 32;
    long zs = (long)blockIdx.z * srcZ;
    long zd = (long)(blockIdx.z / Z2) * dstZ1 + (long)(blockIdx.z % Z2) * dstZ2;
    int tx = threadIdx.x, ty = threadIdx.y;   // (16,16)
    #pragma unroll
    for (int i = 0; i < 2; i++) {
        int r = ty + i * 16;
        float2 v = *reinterpret_cast<const float2*>(&src[zs + (long)(r0 + r) * C + c0 + tx*2]);
        t[tx*2][r] = v.x;
        t[tx*2+1][r] = v.y;
    }
    __syncthreads();
    #pragma unroll
    for (int i = 0; i < 2; i++) {
        int cc = ty + i * 16;
        float a0 = t[cc][tx*2], a1 = t[cc][tx*2+1];
        bf16 h0, l0, h1, l1;
        split_bf16(a0, h0, l0);
        split_bf16(a1, h1, l1);
        long o = zd + (long)(c0 + cc) * R + r0 + tx*2;
        *reinterpret_cast<__nv_bfloat162*>(&dhi[o]) = __nv_bfloat162(h0, h1);
        *reinterpret_cast<__nv_bfloat162*>(&dlo[o]) = __nv_bfloat162(l0, l1);
    }
}

// ======================= HMMA split-bf16 GEMM (round-5 proven config) =======================
template<int TM>
__device__ __forceinline__ void load_chunk(
    uint32_t base, const bf16* __restrict__ Ah, const bf16* __restrict__ Al,
    const bf16* __restrict__ Bh, const bf16* __restrict__ Bl,
    int m0, int n0, int N, int K, int c, int tid)
{
    const uint32_t A_BYTES = TM * TROW;
    const uint32_t BUF = (2 * TM + 256) * TROW;
    uint32_t bb = base + (uint32_t)(c & 1) * BUF;
    int k0 = c << 5;
    #pragma unroll
    for (int i = 0; i < TM/64; i++) {
        int ci  = tid + i * 256;
        int row = ci >> 2, kq = ci & 3;
        uint32_t doff = (uint32_t)(row * TROW + kq * 16);
        long aoff = (long)(m0 + row) * K + k0 + kq * 8;
        cp16(bb + doff, Ah + aoff);
        cp16(bb + A_BYTES + doff, Al + aoff);
    }
    #pragma unroll
    for (int i = 0; i < 2; i++) {
        int ci  = tid + i * 256;
        int row = ci >> 2, kq = ci & 3;
        uint32_t doff = (uint32_t)(row * TROW + kq * 16);
        int nr = n0 + row;
        if (nr < N) {
            long boff = (long)nr * K + k0 + kq * 8;
            cp16(bb + 2*A_BYTES + doff, Bh + boff);
            cp16(bb + 2*A_BYTES + 128*TROW + doff, Bl + boff);
        } else {
            zero16(bb + 2*A_BYTES + doff);
            zero16(bb + 2*A_BYTES + 128*TROW + doff);
        }
    }
}

template<int MI, int OUT>
__global__ __launch_bounds__(256, 2) void gemm_hmma(
    const bf16* __restrict__ Ah, const bf16* __restrict__ Al,
    const bf16* __restrict__ Bh, const bf16* __restrict__ Bl,
    const float* __restrict__ bias, float* __restrict__ C,
    bf16* __restrict__ Oh, bf16* __restrict__ Ol,
    int N, int K)
{
    constexpr int TM = MI * 32;
    const uint32_t A_BYTES = TM * TROW;
    const uint32_t BUF = (2 * TM + 256) * TROW;
    extern __shared__ char smem[];
    const uint32_t base = smem_u32(smem);
    const int tid  = threadIdx.x;
    const int lane = tid & 31;
    const int w    = tid >> 5;
    const int wm   = w & 1;
    const int wn   = w >> 1;
    const int m0 = blockIdx.x * TM, n0 = blockIdx.y * 128;
    const int nCh = K >> 5;

    float acc[MI][4][4];
    #pragma unroll
    for (int i = 0; i < MI; i++)
        #pragma unroll
        for (int j = 0; j < 4; j++)
            #pragma unroll
            for (int q = 0; q < 4; q++) acc[i][j][q] = 0.f;

    const uint32_t a_loff = (uint32_t)((lane & 15) * TROW + ((lane >> 4) << 3) * 2);
    const uint32_t b_loff = (uint32_t)((((lane & 7) + ((lane & 16) ? 8 : 0)) * TROW) +
                                       ((lane & 8) ? 16 : 0));

    load_chunk<TM>(base, Ah, Al, Bh, Bl, m0, n0, N, K, 0, tid);
    cp_commit();

    for (int c = 0; c < nCh; c++) {
        if (c + 1 < nCh) {
            load_chunk<TM>(base, Ah, Al, Bh, Bl, m0, n0, N, K, c + 1, tid);
            cp_commit();
            asm volatile("cp.async.wait_group 1;" ::: "memory");
        } else {
            asm volatile("cp.async.wait_group 0;" ::: "memory");
        }
        __syncthreads();

        uint32_t bb = base + (uint32_t)(c & 1) * BUF;
        uint32_t aH = bb + (uint32_t)(wm * (MI * 16)) * TROW;
        uint32_t aL = aH + A_BYTES;
        uint32_t bH = bb + 2 * A_BYTES + (uint32_t)(wn * 32) * TROW;
        uint32_t bL = bH + 128 * TROW;

        #pragma unroll
        for (int ks = 0; ks < 2; ks++) {
            const uint32_t koff = (uint32_t)(ks * 32);
            uint32_t bh[2][4], bl[2][4];
            #pragma unroll
            for (int g = 0; g < 2; g++) {
                ldm4(bH + (uint32_t)(g * 16) * TROW + b_loff + koff, bh[g]);
                ldm4(bL + (uint32_t)(g * 16) * TROW + b_loff + koff, bl[g]);
            }
            #pragma unroll
            for (int mi = 0; mi < MI; mi++) {
                uint32_t ah[4], al[4];
                ldm4(aH + (uint32_t)(mi * 16) * TROW + a_loff + koff, ah);
                ldm4(aL + (uint32_t)(mi * 16) * TROW + a_loff + koff, al);
                #pragma unroll
                for (int ni = 0; ni < 4; ni++) {
                    const int g = ni >> 1, o = (ni & 1) * 2;
                    mma16816(acc[mi][ni], ah, bh[g][o], bh[g][o + 1]);
                    mma16816(acc[mi][ni], ah, bl[g][o], bl[g][o + 1]);
                    mma16816(acc[mi][ni], al, bh[g][o], bh[g][o + 1]);
                }
            }
        }
        __syncthreads();
    }

    // epilogue
    #pragma unroll
    for (int mi = 0; mi < MI; mi++) {
        int row = m0 + wm * (MI * 16) + mi * 16 + (lane >> 2);
        #pragma unroll
        for (int ni = 0; ni < 4; ni++) {
            int col = n0 + wn * 32 + ni * 8 + ((lane & 3) << 1);
            if (col < N) {
                float bx = bias[col], by = bias[col + 1];
                float v00 = acc[mi][ni][0] + bx, v01 = acc[mi][ni][1] + by;
                float v10 = acc[mi][ni][2] + bx, v11 = acc[mi][ni][3] + by;
                if (OUT == 0) {
                    *reinterpret_cast<float2*>(C + (long)row * N + col)       = make_float2(v00, v01);
                    *reinterpret_cast<float2*>(C + (long)(row + 8) * N + col) = make_float2(v10, v11);
                } else {
                    bf16 h0,l0,h1,l1,h2,l2,h3,l3;
                    split_bf16(v00, h0, l0); split_bf16(v01, h1, l1);
                    split_bf16(v10, h2, l2); split_bf16(v11, h3, l3);
                    *reinterpret_cast<__nv_bfloat162*>(Oh + (long)row * N + col)       = __nv_bfloat162(h0, h1);
                    *reinterpret_cast<__nv_bfloat162*>(Ol + (long)row * N + col)       = __nv_bfloat162(l0, l1);
                    *reinterpret_cast<__nv_bfloat162*>(Oh + (long)(row + 8) * N + col) = __nv_bfloat162(h2, h3);
                    *reinterpret_cast<__nv_bfloat162*>(Ol + (long)(row + 8) * N + col) = __nv_bfloat162(l2, l3);
                }
            }
        }
    }
}

// ======================= attention v2: one block per (b,h), K/V in smem =======================
// 128 threads = 1 per query. Online softmax, q-row + output accumulator in registers.
// dyn smem: Ks[128*64] fp32 (32KB) | Vs[128*64] fp32 (32KB) | keep[128] int (512B)
#define ATT_SMEM (SS*HD*4*2 + SS*4)

__global__ __launch_bounds__(128) void attn_kernel2(const int* __restrict__ ignore,
                                                    bf16* __restrict__ oh,
                                                    bf16* __restrict__ ol) {
    extern __shared__ float sm[];
    float* Ks = sm;                 // [128][64]
    float* Vs = sm + SS*HD;         // [128][64]
    int*   kp = (int*)(sm + 2*SS*HD);
    const int b = blockIdx.x / HH;
    const int h = blockIdx.x % HH;
    const int t = threadIdx.x;      // query index
    const int QW = 3 * DD;
    const long headoff = (long)b * SS * QW + h * HD;

    // stage K and V head tiles: 128 rows x 64 floats, float4 loads
    #pragma unroll
    for (int i = 0; i < 16; i++) {
        int idx = t + i * 128;            // 0..2047
        int row = idx >> 4, f4 = (idx & 15) << 2;
        *reinterpret_cast<float4*>(&Ks[row * HD + f4]) =
            *reinterpret_cast<const float4*>(&g_qkv[headoff + (long)row * QW + DD + f4]);
        *reinterpret_cast<float4*>(&Vs[row * HD + f4]) =
            *reinterpret_cast<const float4*>(&g_qkv[headoff + (long)row * QW + 2*DD + f4]);
    }
    kp[t] = (ignore[b * SS + t] == 0);

    // q row into registers
    float qr[HD];
    #pragma unroll
    for (int e = 0; e < HD; e += 4) {
        float4 v = *reinterpret_cast<const float4*>(&g_qkv[headoff + (long)t * QW + e]);
        qr[e] = v.x; qr[e+1] = v.y; qr[e+2] = v.z; qr[e+3] = v.w;
    }
    __syncthreads();

    float m = -INFINITY, s = 0.f;
    float out[HD];
    #pragma unroll
    for (int e = 0; e < HD; e++) out[e] = 0.f;

    for (int k = 0; k <= t; k++) {
        if (!(kp[k] || k == t)) continue;
        float d = 0.f;
        const float* kr = &Ks[k * HD];
        #pragma unroll
        for (int e = 0; e < HD; e += 4) {
            float4 kv = *reinterpret_cast<const float4*>(kr + e);
            d += qr[e]*kv.x + qr[e+1]*kv.y + qr[e+2]*kv.z + qr[e+3]*kv.w;
        }
        d *= 0.125f;
        if (d > m) {
            float sc = __expf(m - d);    // 0 when m = -inf
            s *= sc;
            #pragma unroll
            for (int e = 0; e < HD; e++) out[e] *= sc;
            m = d;
        }
        float p = __expf(d - m);
        s += p;
        const float* vr = &Vs[k * HD];
        #pragma unroll
        for (int e = 0; e < HD; e += 4) {
            float4 vv = *reinterpret_cast<const float4*>(vr + e);
            out[e]   += p * vv.x;
            out[e+1] += p * vv.y;
            out[e+2] += p * vv.z;
            out[e+3] += p * vv.w;
        }
    }
    const float inv = 1.f / s;
    long oidx = (long)(b * SS + t) * DD + h * HD;
    #pragma unroll
    for (int e = 0; e < HD; e += 2) {
        float v0 = out[e] * inv, v1 = out[e+1] * inv;
        bf16 h0, l0, h1, l1;
        split_bf16(v0, h0, l0);
        split_bf16(v1, h1, l1);
        *reinterpret_cast<__nv_bfloat162*>(&oh[oidx + e]) = __nv_bfloat162(h0, h1);
        *reinterpret_cast<__nv_bfloat162*>(&ol[oidx + e]) = __nv_bfloat162(l0, l1);
    }
}

// ======================= residual (+GELU) + LayerNorm + split =======================
__global__ __launch_bounds__(256) void add_ln_kernel(
    const float* __restrict__ res_in,
    const float* __restrict__ w, const float* __restrict__ bvec,
    bf16* __restrict__ ah, bf16* __restrict__ al,
    int dogelu) {
    const int row = blockIdx.x;
    const int t = threadIdx.x;
    __shared__ float red[256];

    float vals[3];
    float sum = 0.f;
    #pragma unroll
    for (int i = 0; i < 3; i++) {
        int d = t + i * 256;
        float r = res_in[(long)row * DD + d];
        if (dogelu) r = 0.5f * r * (1.f + erff(r * 0.70710678118f));
        float v = g_h[(long)row * DD + d] + r;
        vals[i] = v;
        sum += v;
    }
    red[t] = sum; __syncthreads();
    for (int off = 128; off > 0; off >>= 1) {
        if (t < off) red[t] += red[t + off];
        __syncthreads();
    }
    const float mean = red[0] * (1.f / DD);
    __syncthreads();
    float vs = 0.f;
    #pragma unroll
    for (int i = 0; i < 3; i++) { float dv = vals[i] - mean; vs += dv * dv; }
    red[t] = vs; __syncthreads();
    for (int off = 128; off > 0; off >>= 1) {
        if (t < off) red[t] += red[t + off];
        __syncthreads();
    }
    const float rstd = rsqrtf(red[0] * (1.f / DD) + 1e-5f);
    #pragma unroll
    for (int i = 0; i < 3; i++) {
        int d = t + i * 256;
        float v = (vals[i] - mean) * rstd * w[d] + bvec[d];
        g_h[(long)row * DD + d] = v;
        bf16 hh, ll; split_bf16(v, hh, ll);
        ah[(long)row * DD + d] = hh;
        al[(long)row * DD + d] = ll;
    }
}

// ======================= host orchestration =======================
extern "C" void kernel_launch(void* const* d_in, const int* in_sizes, int n_in,
                              void* d_out, int out_size) {
    const int*   x    = (const int*)  d_in[0];
    const int*   ign  = (const int*)  d_in[1];
    const float* bpe  = (const float*)d_in[2];
    const float* pe   = (const float*)d_in[3];
    const float* Wq   = (const float*)d_in[4];
    const float* bq   = (const float*)d_in[5];
    const float* Wk   = (const float*)d_in[6];
    const float* bk   = (const float*)d_in[7];
    const float* Wv   = (const float*)d_in[8];
    const float* bv   = (const float*)d_in[9];
    const float* Wo   = (const float*)d_in[10];
    const float* bo   = (const float*)d_in[11];
    const float* W1   = (const float*)d_in[12];
    const float* b1   = (const float*)d_in[13];
    const float* W2   = (const float*)d_in[14];
    const float* b2   = (const float*)d_in[15];
    const float* ln1w = (const float*)d_in[16];
    const float* ln1b = (const float*)d_in[17];
    const float* ln2w = (const float*)d_in[18];
    const float* ln2b = (const float*)d_in[19];
    const float* Wout = (const float*)d_in[20];
    const float* bout = (const float*)d_in[21];
    float* out = (float*)d_out;

    float *gh, *gqkv, *gproj, *gff2, *gbqkv;
    cudaGetSymbolAddress((void**)&gh,    g_h);
    cudaGetSymbolAddress((void**)&gqkv,  g_qkv);
    cudaGetSymbolAddress((void**)&gproj, g_proj);
    cudaGetSymbolAddress((void**)&gff2,  g_ff2);
    cudaGetSymbolAddress((void**)&gbqkv, g_bqkv);

    bf16 *wqkv_h, *wo_h, *w1_h, *w2_h, *wout_h, *actA_h, *actB_h;
    bf16 *wqkv_l, *wo_l, *w1_l, *w2_l, *wout_l, *actA_l, *actB_l;
    void* p;
    cudaGetSymbolAddress(&p, s_wqkv); wqkv_h = (bf16*)p; wqkv_l = wqkv_h + (long)LL*3*DD*DD;
    cudaGetSymbolAddress(&p, s_wo);   wo_h = (bf16*)p;   wo_l   = wo_h   + (long)LL*DD*DD;
    cudaGetSymbolAddress(&p, s_w1);   w1_h = (bf16*)p;   w1_l   = w1_h   + (long)LL*DD*FF;
    cudaGetSymbolAddress(&p, s_w2);   w2_h = (bf16*)p;   w2_l   = w2_h   + (long)LL*FF*DD;
    cudaGetSymbolAddress(&p, s_wout); wout_h = (bf16*)p; wout_l = wout_h + (long)VV*DD;
    cudaGetSymbolAddress(&p, s_actA); actA_h = (bf16*)p; actA_l = actA_h + (long)BB*SS*FF;
    cudaGetSymbolAddress(&p, s_actB); actB_h = (bf16*)p; actB_l = actB_h + (long)BB*SS*FF;

    const int SM128 = (2*128 + 256) * TROW * 2;   // 81920
    const int SM64  = (2*64  + 256) * TROW * 2;   // 61440
    cudaFuncSetAttribute(gemm_hmma<4,0>, cudaFuncAttributeMaxDynamicSharedMemorySize, SM128);
    cudaFuncSetAttribute(gemm_hmma<4,1>, cudaFuncAttributeMaxDynamicSharedMemorySize, SM128);
    cudaFuncSetAttribute(gemm_hmma<2,0>, cudaFuncAttributeMaxDynamicSharedMemorySize, SM64);
    cudaFuncSetAttribute(attn_kernel2, cudaFuncAttributeMaxDynamicSharedMemorySize, ATT_SMEM);

    const int M = BB * SS;  // 2048
    dim3 tb16(16, 16);

    // ---- weight conversion ----
    conv_transpose<<<dim3(HD/32, DD/32, LL*HH), tb16>>>(Wq, wqkv_h + 0L*DD*DD, wqkv_l + 0L*DD*DD,
        DD, HD, (long)DD*HD, HH, (long)3*DD*DD, (long)HD*DD);
    conv_transpose<<<dim3(HD/32, DD/32, LL*HH), tb16>>>(Wk, wqkv_h + 1L*DD*DD, wqkv_l + 1L*DD*DD,
        DD, HD, (long)DD*HD, HH, (long)3*DD*DD, (long)HD*DD);
    conv_transpose<<<dim3(HD/32, DD/32, LL*HH), tb16>>>(Wv, wqkv_h + 2L*DD*DD, wqkv_l + 2L*DD*DD,
        DD, HD, (long)DD*HD, HH, (long)3*DD*DD, (long)HD*DD);
    conv_transpose<<<dim3(DD/32, DD/32, LL), tb16>>>(Wo, wo_h, wo_l,
        DD, DD, (long)DD*DD, 1, (long)DD*DD, 0);
    conv_transpose<<<dim3(FF/32, DD/32, LL), tb16>>>(W1, w1_h, w1_l,
        DD, FF, (long)DD*FF, 1, (long)DD*FF, 0);
    conv_transpose<<<dim3(DD/32, FF/32, LL), tb16>>>(W2, w2_h, w2_l,
        FF, DD, (long)FF*DD, 1, (long)FF*DD, 0);
    conv_transpose<<<dim3(VV/32, DD/32, 1), tb16>>>(Wout, wout_h, wout_l,
        DD, VV, 0, 1, 0, 0);
    concat_bias<<<(LL*3*DD + 255)/256, 256>>>(bq, bk, bv);

    embed_kernel<<<(BB*SS*DD + 255)/256, 256>>>(x, bpe, pe, actA_h, actA_l);

    for (int l = 0; l < LL; l++) {
        gemm_hmma<4,0><<<dim3(M/128, (3*DD)/128), 256, SM128>>>(actA_h, actA_l,
            wqkv_h + (long)l*3*DD*DD, wqkv_l + (long)l*3*DD*DD,
            gbqkv + (long)l*3*DD, gqkv, nullptr, nullptr, 3*DD, DD);

        attn_kernel2<<<BB*HH, 128, ATT_SMEM>>>(ign, actB_h, actB_l);

        gemm_hmma<2,0><<<dim3(M/64, DD/128), 256, SM64>>>(actB_h, actB_l,
            wo_h + (long)l*DD*DD, wo_l + (long)l*DD*DD,
            bo + (long)l*DD, gproj, nullptr, nullptr, DD, DD);
        add_ln_kernel<<<M, 256>>>(gproj, ln1w + (long)l*DD, ln1b + (long)l*DD,
                                  actA_h, actA_l, 0);

        gemm_hmma<4,1><<<dim3(M/128, FF/128), 256, SM128>>>(actA_h, actA_l,
            w1_h + (long)l*DD*FF, w1_l + (long)l*DD*FF,
            b1 + (long)l*FF, nullptr, actB_h, actB_l, FF, DD);
        gemm_hmma<2,0><<<dim3(M/64, DD/128), 256, SM64>>>(actB_h, actB_l,
            w2_h + (long)l*FF*DD, w2_l + (long)l*FF*DD,
            b2 + (long)l*DD, gff2, nullptr, nullptr, DD, FF);
        add_ln_kernel<<<M, 256>>>(gff2, ln2w + (long)l*DD, ln2b + (long)l*DD,
                                  actA_h, actA_l, 1);
    }

    gemm_hmma<4,0><<<dim3(M/128, (VV + 127)/128), 256, SM128>>>(actA_h, actA_l,
        wout_h, wout_l, bout, out, nullptr, nullptr, VV, DD);
}

// round 10
// speedup vs baseline: 2.0118x; 1.4194x over previous
#include <cuda_runtime.h>
#include <cuda_bf16.h>
#include <math.h>
#include <stdint.h>

#define BB 16
#define SS 128
#define VV 40000
#define DD 768
#define HH 12
#define HD 64
#define FF 3072
#define LL 12

typedef __nv_bfloat16 bf16;

// ---------------- fp32 scratch ----------------
__device__ float g_h   [BB*SS*DD];
__device__ float g_qkv [BB*SS*3*DD];   // [which][b][h][s][e] head-contiguous
__device__ float g_proj[BB*SS*DD];
__device__ float g_ff2 [BB*SS*DD];
__device__ float g_bqkv[LL*3*DD];

#define QKV_PLANE (BB*SS*DD)

// ---------------- bf16 split weights [N][K] ----------------
__device__ bf16 s_wqkv[2][LL*3*DD*DD];
__device__ bf16 s_wo  [2][LL*DD*DD];
__device__ bf16 s_w1  [2][LL*DD*FF];
__device__ bf16 s_w2  [2][LL*FF*DD];
__device__ bf16 s_wout[2][VV*DD];
__device__ bf16 s_actA[2][BB*SS*FF];
__device__ bf16 s_actB[2][BB*SS*FF];

// ======================= helpers =======================
__device__ __forceinline__ uint32_t smem_u32(const void* p) {
    uint32_t a;
    asm("{ .reg .u64 t; cvta.to.shared.u64 t, %1; cvt.u32.u64 %0, t; }" : "=r"(a) : "l"(p));
    return a;
}
__device__ __forceinline__ void cp16(uint32_t dst, const void* src) {
    asm volatile("cp.async.cg.shared.global [%0], [%1], 16;" :: "r"(dst), "l"(src) : "memory");
}
__device__ __forceinline__ void zero16(uint32_t dst) {
    asm volatile("st.shared.v4.b32 [%0], {%1,%1,%1,%1};" :: "r"(dst), "r"(0u) : "memory");
}
__device__ __forceinline__ void cp_commit() {
    asm volatile("cp.async.commit_group;" ::: "memory");
}
__device__ __forceinline__ void ldm4(uint32_t addr, uint32_t* r) {
    asm volatile("ldmatrix.sync.aligned.m8n8.x4.shared.b16 {%0,%1,%2,%3}, [%4];"
                 : "=r"(r[0]), "=r"(r[1]), "=r"(r[2]), "=r"(r[3]) : "r"(addr));
}
__device__ __forceinline__ void mma16816(float* d, const uint32_t* a, uint32_t b0, uint32_t b1) {
    asm volatile(
        "mma.sync.aligned.m16n8k16.row.col.f32.bf16.bf16.f32 "
        "{%0,%1,%2,%3}, {%4,%5,%6,%7}, {%8,%9}, {%0,%1,%2,%3};"
        : "+f"(d[0]), "+f"(d[1]), "+f"(d[2]), "+f"(d[3])
        : "r"(a[0]), "r"(a[1]), "r"(a[2]), "r"(a[3]), "r"(b0), "r"(b1));
}
__device__ __forceinline__ void split_bf16(float v, bf16& h, bf16& l) {
    h = __float2bfloat16(v);
    l = __float2bfloat16(v - __bfloat162float(h));
}

#define TROW 80

// ======================= small kernels =======================
__global__ void embed_kernel(const int* __restrict__ x,
                             const float* __restrict__ bpe,
                             const float* __restrict__ pe,
                             bf16* __restrict__ ah, bf16* __restrict__ al) {
    int idx = blockIdx.x * blockDim.x + threadIdx.x;
    if (idx >= BB*SS*DD) return;
    int d  = idx % DD;
    int bs = idx / DD;
    int s  = bs % SS;
    int tok = x[bs];
    float v = bpe[(long)tok*DD + d] + pe[s*DD + d];
    g_h[idx] = v;
    bf16 h, l; split_bf16(v, h, l);
    ah[idx] = h; al[idx] = l;
}

__global__ void concat_bias(const float* __restrict__ bq, const float* __restrict__ bk,
                            const float* __restrict__ bv) {
    int idx = blockIdx.x * blockDim.x + threadIdx.x;
    if (idx >= LL*3*DD) return;
    int l = idx / (3*DD), n = idx % (3*DD);
    float v;
    if (n < DD)          v = bq[l*DD + n];
    else if (n < 2*DD)   v = bk[l*DD + n - DD];
    else                 v = bv[l*DD + n - 2*DD];
    g_bqkv[idx] = v;
}

__global__ void conv_transpose(const float* __restrict__ src, bf16* __restrict__ dhi,
                               bf16* __restrict__ dlo, int R, int C,
                               long srcZ, int Z2, long dstZ1, long dstZ2) {
    __shared__ float t[32][33];
    int c0 = blockIdx.x * 32, r0 = blockIdx.y * 32;
    long zs = (long)blockIdx.z * srcZ;
    long zd = (long)(blockIdx.z / Z2) * dstZ1 + (long)(blockIdx.z % Z2) * dstZ2;
    int tx = threadIdx.x, ty = threadIdx.y;   // (16,16)
    #pragma unroll
    for (int i = 0; i < 2; i++) {
        int r = ty + i * 16;
        float2 v = *reinterpret_cast<const float2*>(&src[zs + (long)(r0 + r) * C + c0 + tx*2]);
        t[tx*2][r] = v.x;
        t[tx*2+1][r] = v.y;
    }
    __syncthreads();
    #pragma unroll
    for (int i = 0; i < 2; i++) {
        int cc = ty + i * 16;
        float a0 = t[cc][tx*2], a1 = t[cc][tx*2+1];
        bf16 h0, l0, h1, l1;
        split_bf16(a0, h0, l0);
        split_bf16(a1, h1, l1);
        long o = zd + (long)(c0 + cc) * R + r0 + tx*2;
        *reinterpret_cast<__nv_bfloat162*>(&dhi[o]) = __nv_bfloat162(h0, h1);
        *reinterpret_cast<__nv_bfloat162*>(&dlo[o]) = __nv_bfloat162(l0, l1);
    }
}

// ======================= HMMA split-bf16 GEMM (round-5 proven config) =======================
// OUT: 0 = fp32 C row-major; 1 = bf16 hi/lo pair; 2 = QKV scatter to [which][b][h][s][e]
template<int TM>
__device__ __forceinline__ void load_chunk(
    uint32_t base, const bf16* __restrict__ Ah, const bf16* __restrict__ Al,
    const bf16* __restrict__ Bh, const bf16* __restrict__ Bl,
    int m0, int n0, int N, int K, int c, int tid)
{
    const uint32_t A_BYTES = TM * TROW;
    const uint32_t BUF = (2 * TM + 256) * TROW;
    uint32_t bb = base + (uint32_t)(c & 1) * BUF;
    int k0 = c << 5;
    #pragma unroll
    for (int i = 0; i < TM/64; i++) {
        int ci  = tid + i * 256;
        int row = ci >> 2, kq = ci & 3;
        uint32_t doff = (uint32_t)(row * TROW + kq * 16);
        long aoff = (long)(m0 + row) * K + k0 + kq * 8;
        cp16(bb + doff, Ah + aoff);
        cp16(bb + A_BYTES + doff, Al + aoff);
    }
    #pragma unroll
    for (int i = 0; i < 2; i++) {
        int ci  = tid + i * 256;
        int row = ci >> 2, kq = ci & 3;
        uint32_t doff = (uint32_t)(row * TROW + kq * 16);
        int nr = n0 + row;
        if (nr < N) {
            long boff = (long)nr * K + k0 + kq * 8;
            cp16(bb + 2*A_BYTES + doff, Bh + boff);
            cp16(bb + 2*A_BYTES + 128*TROW + doff, Bl + boff);
        } else {
            zero16(bb + 2*A_BYTES + doff);
            zero16(bb + 2*A_BYTES + 128*TROW + doff);
        }
    }
}

__device__ __forceinline__ long qkv_addr(int row, int col) {
    // row = b*SS + s ; col = which*768 + h*64 + e
    int b = row >> 7, s = row & (SS - 1);
    int which = col / DD;
    int rem = col - which * DD;
    int h = rem >> 6, e = rem & 63;
    return (long)which * QKV_PLANE + (((long)(b * HH + h) * SS + s) * HD) + e;
}

template<int MI, int OUT>
__global__ __launch_bounds__(256, 2) void gemm_hmma(
    const bf16* __restrict__ Ah, const bf16* __restrict__ Al,
    const bf16* __restrict__ Bh, const bf16* __restrict__ Bl,
    const float* __restrict__ bias, float* __restrict__ C,
    bf16* __restrict__ Oh, bf16* __restrict__ Ol,
    int N, int K)
{
    constexpr int TM = MI * 32;
    const uint32_t A_BYTES = TM * TROW;
    const uint32_t BUF = (2 * TM + 256) * TROW;
    extern __shared__ char smem[];
    const uint32_t base = smem_u32(smem);
    const int tid  = threadIdx.x;
    const int lane = tid & 31;
    const int w    = tid >> 5;
    const int wm   = w & 1;
    const int wn   = w >> 1;
    const int m0 = blockIdx.x * TM, n0 = blockIdx.y * 128;
    const int nCh = K >> 5;

    float acc[MI][4][4];
    #pragma unroll
    for (int i = 0; i < MI; i++)
        #pragma unroll
        for (int j = 0; j < 4; j++)
            #pragma unroll
            for (int q = 0; q < 4; q++) acc[i][j][q] = 0.f;

    const uint32_t a_loff = (uint32_t)((lane & 15) * TROW + ((lane >> 4) << 3) * 2);
    const uint32_t b_loff = (uint32_t)((((lane & 7) + ((lane & 16) ? 8 : 0)) * TROW) +
                                       ((lane & 8) ? 16 : 0));

    load_chunk<TM>(base, Ah, Al, Bh, Bl, m0, n0, N, K, 0, tid);
    cp_commit();

    for (int c = 0; c < nCh; c++) {
        if (c + 1 < nCh) {
            load_chunk<TM>(base, Ah, Al, Bh, Bl, m0, n0, N, K, c + 1, tid);
            cp_commit();
            asm volatile("cp.async.wait_group 1;" ::: "memory");
        } else {
            asm volatile("cp.async.wait_group 0;" ::: "memory");
        }
        __syncthreads();

        uint32_t bb = base + (uint32_t)(c & 1) * BUF;
        uint32_t aH = bb + (uint32_t)(wm * (MI * 16)) * TROW;
        uint32_t aL = aH + A_BYTES;
        uint32_t bH = bb + 2 * A_BYTES + (uint32_t)(wn * 32) * TROW;
        uint32_t bL = bH + 128 * TROW;

        #pragma unroll
        for (int ks = 0; ks < 2; ks++) {
            const uint32_t koff = (uint32_t)(ks * 32);
            uint32_t bh[2][4], bl[2][4];
            #pragma unroll
            for (int g = 0; g < 2; g++) {
                ldm4(bH + (uint32_t)(g * 16) * TROW + b_loff + koff, bh[g]);
                ldm4(bL + (uint32_t)(g * 16) * TROW + b_loff + koff, bl[g]);
            }
            #pragma unroll
            for (int mi = 0; mi < MI; mi++) {
                uint32_t ah[4], al[4];
                ldm4(aH + (uint32_t)(mi * 16) * TROW + a_loff + koff, ah);
                ldm4(aL + (uint32_t)(mi * 16) * TROW + a_loff + koff, al);
                #pragma unroll
                for (int ni = 0; ni < 4; ni++) {
                    const int g = ni >> 1, o = (ni & 1) * 2;
                    mma16816(acc[mi][ni], ah, bh[g][o], bh[g][o + 1]);
                    mma16816(acc[mi][ni], ah, bl[g][o], bl[g][o + 1]);
                    mma16816(acc[mi][ni], al, bh[g][o], bh[g][o + 1]);
                }
            }
        }
        __syncthreads();
    }

    // epilogue
    #pragma unroll
    for (int mi = 0; mi < MI; mi++) {
        int row = m0 + wm * (MI * 16) + mi * 16 + (lane >> 2);
        #pragma unroll
        for (int ni = 0; ni < 4; ni++) {
            int col = n0 + wn * 32 + ni * 8 + ((lane & 3) << 1);
            if (col < N) {
                float bx = bias[col], by = bias[col + 1];
                float v00 = acc[mi][ni][0] + bx, v01 = acc[mi][ni][1] + by;
                float v10 = acc[mi][ni][2] + bx, v11 = acc[mi][ni][3] + by;
                if (OUT == 0) {
                    *reinterpret_cast<float2*>(C + (long)row * N + col)       = make_float2(v00, v01);
                    *reinterpret_cast<float2*>(C + (long)(row + 8) * N + col) = make_float2(v10, v11);
                } else if (OUT == 2) {
                    long a0 = qkv_addr(row, col);          // e even, e+1 same head
                    *reinterpret_cast<float2*>(C + a0)            = make_float2(v00, v01);
                    *reinterpret_cast<float2*>(C + a0 + 8 * HD)   = make_float2(v10, v11);
                } else {
                    bf16 h0,l0,h1,l1,h2,l2,h3,l3;
                    split_bf16(v00, h0, l0); split_bf16(v01, h1, l1);
                    split_bf16(v10, h2, l2); split_bf16(v11, h3, l3);
                    *reinterpret_cast<__nv_bfloat162*>(Oh + (long)row * N + col)       = __nv_bfloat162(h0, h1);
                    *reinterpret_cast<__nv_bfloat162*>(Ol + (long)row * N + col)       = __nv_bfloat162(l0, l1);
                    *reinterpret_cast<__nv_bfloat162*>(Oh + (long)(row + 8) * N + col) = __nv_bfloat162(h2, h3);
                    *reinterpret_cast<__nv_bfloat162*>(Ol + (long)(row + 8) * N + col) = __nv_bfloat162(l2, l3);
                }
            }
        }
    }
}

// ======================= attention v3: per-query block, head-contiguous KV =======================
__global__ __launch_bounds__(128) void attn_kernel3(const int* __restrict__ ignore,
                                                    bf16* __restrict__ oh,
                                                    bf16* __restrict__ ol) {
    const int qi = blockIdx.x & (SS - 1);
    const int h  = (blockIdx.x >> 7) % HH;
    const int b  = blockIdx.x / (SS * HH);
    const int t  = threadIdx.x;

    __shared__ float qrow[HD];
    __shared__ float p[SS];
    __shared__ float red[SS];

    const long headoff = (long)(b * HH + h) * SS * HD;   // base of [b][h]
    const float* Q = g_qkv + 0L * QKV_PLANE + headoff;
    const float* K = g_qkv + 1L * QKV_PLANE + headoff;
    const float* V = g_qkv + 2L * QKV_PLANE + headoff;

    if (t < HD) qrow[t] = Q[(long)qi * HD + t];
    __syncthreads();

    const bool allowed = (t <= qi) && (ignore[b * SS + t] == 0 || t == qi);
    float score = -INFINITY;
    if (allowed) {
        const float* kptr = K + (long)t * HD;
        float s = 0.f;
        #pragma unroll
        for (int e = 0; e < HD; e += 4) {
            float4 kv = *reinterpret_cast<const float4*>(kptr + e);
            s += qrow[e]*kv.x + qrow[e+1]*kv.y + qrow[e+2]*kv.z + qrow[e+3]*kv.w;
        }
        score = s * 0.125f;
    }
    red[t] = score; __syncthreads();
    for (int off = 64; off > 0; off >>= 1) {
        if (t < off) red[t] = fmaxf(red[t], red[t + off]);
        __syncthreads();
    }
    const float mx = red[0];
    __syncthreads();
    const float e = allowed ? expf(score - mx) : 0.f;
    p[t] = e; red[t] = e; __syncthreads();
    for (int off = 64; off > 0; off >>= 1) {
        if (t < off) red[t] += red[t + off];
        __syncthreads();
    }
    const float inv = 1.f / red[0];
    if (t < HD) {
        const float* vbase = V + t;
        float o = 0.f;
        #pragma unroll 8
        for (int k = 0; k <= qi; k++) o += p[k] * vbase[(long)k * HD];
        o *= inv;
        long oidx = (long)(b * SS + qi) * DD + h * HD + t;
        bf16 hh, ll; split_bf16(o, hh, ll);
        oh[oidx] = hh; ol[oidx] = ll;
    }
}

// ======================= residual (+GELU) + LayerNorm + split =======================
__global__ __launch_bounds__(256) void add_ln_kernel(
    const float* __restrict__ res_in,
    const float* __restrict__ w, const float* __restrict__ bvec,
    bf16* __restrict__ ah, bf16* __restrict__ al,
    int dogelu) {
    const int row = blockIdx.x;
    const int t = threadIdx.x;
    __shared__ float red[256];

    float vals[3];
    float sum = 0.f;
    #pragma unroll
    for (int i = 0; i < 3; i++) {
        int d = t + i * 256;
        float r = res_in[(long)row * DD + d];
        if (dogelu) r = 0.5f * r * (1.f + erff(r * 0.70710678118f));
        float v = g_h[(long)row * DD + d] + r;
        vals[i] = v;
        sum += v;
    }
    red[t] = sum; __syncthreads();
    for (int off = 128; off > 0; off >>= 1) {
        if (t < off) red[t] += red[t + off];
        __syncthreads();
    }
    const float mean = red[0] * (1.f / DD);
    __syncthreads();
    float vs = 0.f;
    #pragma unroll
    for (int i = 0; i < 3; i++) { float dv = vals[i] - mean; vs += dv * dv; }
    red[t] = vs; __syncthreads();
    for (int off = 128; off > 0; off >>= 1) {
        if (t < off) red[t] += red[t + off];
        __syncthreads();
    }
    const float rstd = rsqrtf(red[0] * (1.f / DD) + 1e-5f);
    #pragma unroll
    for (int i = 0; i < 3; i++) {
        int d = t + i * 256;
        float v = (vals[i] - mean) * rstd * w[d] + bvec[d];
        g_h[(long)row * DD + d] = v;
        bf16 hh, ll; split_bf16(v, hh, ll);
        ah[(long)row * DD + d] = hh;
        al[(long)row * DD + d] = ll;
    }
}

// ======================= host orchestration =======================
extern "C" void kernel_launch(void* const* d_in, const int* in_sizes, int n_in,
                              void* d_out, int out_size) {
    const int*   x    = (const int*)  d_in[0];
    const int*   ign  = (const int*)  d_in[1];
    const float* bpe  = (const float*)d_in[2];
    const float* pe   = (const float*)d_in[3];
    const float* Wq   = (const float*)d_in[4];
    const float* bq   = (const float*)d_in[5];
    const float* Wk   = (const float*)d_in[6];
    const float* bk   = (const float*)d_in[7];
    const float* Wv   = (const float*)d_in[8];
    const float* bv   = (const float*)d_in[9];
    const float* Wo   = (const float*)d_in[10];
    const float* bo   = (const float*)d_in[11];
    const float* W1   = (const float*)d_in[12];
    const float* b1   = (const float*)d_in[13];
    const float* W2   = (const float*)d_in[14];
    const float* b2   = (const float*)d_in[15];
    const float* ln1w = (const float*)d_in[16];
    const float* ln1b = (const float*)d_in[17];
    const float* ln2w = (const float*)d_in[18];
    const float* ln2b = (const float*)d_in[19];
    const float* Wout = (const float*)d_in[20];
    const float* bout = (const float*)d_in[21];
    float* out = (float*)d_out;

    float *gh, *gqkv, *gproj, *gff2, *gbqkv;
    cudaGetSymbolAddress((void**)&gh,    g_h);
    cudaGetSymbolAddress((void**)&gqkv,  g_qkv);
    cudaGetSymbolAddress((void**)&gproj, g_proj);
    cudaGetSymbolAddress((void**)&gff2,  g_ff2);
    cudaGetSymbolAddress((void**)&gbqkv, g_bqkv);

    bf16 *wqkv_h, *wo_h, *w1_h, *w2_h, *wout_h, *actA_h, *actB_h;
    bf16 *wqkv_l, *wo_l, *w1_l, *w2_l, *wout_l, *actA_l, *actB_l;
    void* p;
    cudaGetSymbolAddress(&p, s_wqkv); wqkv_h = (bf16*)p; wqkv_l = wqkv_h + (long)LL*3*DD*DD;
    cudaGetSymbolAddress(&p, s_wo);   wo_h = (bf16*)p;   wo_l   = wo_h   + (long)LL*DD*DD;
    cudaGetSymbolAddress(&p, s_w1);   w1_h = (bf16*)p;   w1_l   = w1_h   + (long)LL*DD*FF;
    cudaGetSymbolAddress(&p, s_w2);   w2_h = (bf16*)p;   w2_l   = w2_h   + (long)LL*FF*DD;
    cudaGetSymbolAddress(&p, s_wout); wout_h = (bf16*)p; wout_l = wout_h + (long)VV*DD;
    cudaGetSymbolAddress(&p, s_actA); actA_h = (bf16*)p; actA_l = actA_h + (long)BB*SS*FF;
    cudaGetSymbolAddress(&p, s_actB); actB_h = (bf16*)p; actB_l = actB_h + (long)BB*SS*FF;

    const int SM128 = (2*128 + 256) * TROW * 2;   // 81920
    const int SM64  = (2*64  + 256) * TROW * 2;   // 61440
    cudaFuncSetAttribute(gemm_hmma<4,2>, cudaFuncAttributeMaxDynamicSharedMemorySize, SM128);
    cudaFuncSetAttribute(gemm_hmma<4,0>, cudaFuncAttributeMaxDynamicSharedMemorySize, SM128);
    cudaFuncSetAttribute(gemm_hmma<4,1>, cudaFuncAttributeMaxDynamicSharedMemorySize, SM128);
    cudaFuncSetAttribute(gemm_hmma<2,0>, cudaFuncAttributeMaxDynamicSharedMemorySize, SM64);

    const int M = BB * SS;  // 2048
    dim3 tb16(16, 16);

    // ---- weight conversion ----
    conv_transpose<<<dim3(HD/32, DD/32, LL*HH), tb16>>>(Wq, wqkv_h + 0L*DD*DD, wqkv_l + 0L*DD*DD,
        DD, HD, (long)DD*HD, HH, (long)3*DD*DD, (long)HD*DD);
    conv_transpose<<<dim3(HD/32, DD/32, LL*HH), tb16>>>(Wk, wqkv_h + 1L*DD*DD, wqkv_l + 1L*DD*DD,
        DD, HD, (long)DD*HD, HH, (long)3*DD*DD, (long)HD*DD);
    conv_transpose<<<dim3(HD/32, DD/32, LL*HH), tb16>>>(Wv, wqkv_h + 2L*DD*DD, wqkv_l + 2L*DD*DD,
        DD, HD, (long)DD*HD, HH, (long)3*DD*DD, (long)HD*DD);
    conv_transpose<<<dim3(DD/32, DD/32, LL), tb16>>>(Wo, wo_h, wo_l,
        DD, DD, (long)DD*DD, 1, (long)DD*DD, 0);
    conv_transpose<<<dim3(FF/32, DD/32, LL), tb16>>>(W1, w1_h, w1_l,
        DD, FF, (long)DD*FF, 1, (long)DD*FF, 0);
    conv_transpose<<<dim3(DD/32, FF/32, LL), tb16>>>(W2, w2_h, w2_l,
        FF, DD, (long)FF*DD, 1, (long)FF*DD, 0);
    conv_transpose<<<dim3(VV/32, DD/32, 1), tb16>>>(Wout, wout_h, wout_l,
        DD, VV, 0, 1, 0, 0);
    concat_bias<<<(LL*3*DD + 255)/256, 256>>>(bq, bk, bv);

    embed_kernel<<<(BB*SS*DD + 255)/256, 256>>>(x, bpe, pe, actA_h, actA_l);

    for (int l = 0; l < LL; l++) {
        gemm_hmma<4,2><<<dim3(M/128, (3*DD)/128), 256, SM128>>>(actA_h, actA_l,
            wqkv_h + (long)l*3*DD*DD, wqkv_l + (long)l*3*DD*DD,
            gbqkv + (long)l*3*DD, gqkv, nullptr, nullptr, 3*DD, DD);

        attn_kernel3<<<BB*HH*SS, 128>>>(ign, actB_h, actB_l);

        gemm_hmma<2,0><<<dim3(M/64, DD/128), 256, SM64>>>(actB_h, actB_l,
            wo_h + (long)l*DD*DD, wo_l + (long)l*DD*DD,
            bo + (long)l*DD, gproj, nullptr, nullptr, DD, DD);
        add_ln_kernel<<<M, 256>>>(gproj, ln1w + (long)l*DD, ln1b + (long)l*DD,
                                  actA_h, actA_l, 0);

        gemm_hmma<4,1><<<dim3(M/128, FF/128), 256, SM128>>>(actA_h, actA_l,
            w1_h + (long)l*DD*FF, w1_l + (long)l*DD*FF,
            b1 + (long)l*FF, nullptr, actB_h, actB_l, FF, DD);
        gemm_hmma<2,0><<<dim3(M/64, DD/128), 256, SM64>>>(actB_h, actB_l,
            w2_h + (long)l*FF*DD, w2_l + (long)l*FF*DD,
            b2 + (long)l*DD, gff2, nullptr, nullptr, DD, FF);
        add_ln_kernel<<<M, 256>>>(gff2, ln2w + (long)l*DD, ln2b + (long)l*DD,
                                  actA_h, actA_l, 1);
    }

    gemm_hmma<4,0><<<dim3(M/128, (VV + 127)/128), 256, SM128>>>(actA_h, actA_l,
        wout_h, wout_l, bout, out, nullptr, nullptr, VV, DD);
}

// round 11
// speedup vs baseline: 2.0222x; 1.0052x over previous
#include <cuda_runtime.h>
#include <cuda_bf16.h>
#include <math.h>
#include <stdint.h>

#define BB 16
#define SS 128
#define VV 40000
#define DD 768
#define HH 12
#define HD 64
#define FF 3072
#define LL 12

typedef __nv_bfloat16 bf16;

// ---------------- fp32 scratch ----------------
__device__ float g_h   [BB*SS*DD];
__device__ float g_qkv [BB*SS*3*DD];   // [which][b][h][s][e] head-contiguous
__device__ float g_proj[BB*SS*DD];
__device__ float g_ff2 [BB*SS*DD];
__device__ float g_bqkv[LL*3*DD];

#define QKV_PLANE (BB*SS*DD)

// ---------------- bf16 split weights [N][K] ----------------
__device__ bf16 s_wqkv[2][LL*3*DD*DD];
__device__ bf16 s_wo  [2][LL*DD*DD];
__device__ bf16 s_w1  [2][LL*DD*FF];
__device__ bf16 s_w2  [2][LL*FF*DD];
__device__ bf16 s_wout[2][VV*DD];
__device__ bf16 s_actA[2][BB*SS*FF];
__device__ bf16 s_actB[2][BB*SS*FF];

// ======================= helpers =======================
__device__ __forceinline__ uint32_t smem_u32(const void* p) {
    uint32_t a;
    asm("{ .reg .u64 t; cvta.to.shared.u64 t, %1; cvt.u32.u64 %0, t; }" : "=r"(a) : "l"(p));
    return a;
}
__device__ __forceinline__ void cp16(uint32_t dst, const void* src) {
    asm volatile("cp.async.cg.shared.global [%0], [%1], 16;" :: "r"(dst), "l"(src) : "memory");
}
__device__ __forceinline__ void zero16(uint32_t dst) {
    asm volatile("st.shared.v4.b32 [%0], {%1,%1,%1,%1};" :: "r"(dst), "r"(0u) : "memory");
}
__device__ __forceinline__ void cp_commit() {
    asm volatile("cp.async.commit_group;" ::: "memory");
}
__device__ __forceinline__ void ldm4(uint32_t addr, uint32_t* r) {
    asm volatile("ldmatrix.sync.aligned.m8n8.x4.shared.b16 {%0,%1,%2,%3}, [%4];"
                 : "=r"(r[0]), "=r"(r[1]), "=r"(r[2]), "=r"(r[3]) : "r"(addr));
}
__device__ __forceinline__ void mma16816(float* d, const uint32_t* a, uint32_t b0, uint32_t b1) {
    asm volatile(
        "mma.sync.aligned.m16n8k16.row.col.f32.bf16.bf16.f32 "
        "{%0,%1,%2,%3}, {%4,%5,%6,%7}, {%8,%9}, {%0,%1,%2,%3};"
        : "+f"(d[0]), "+f"(d[1]), "+f"(d[2]), "+f"(d[3])
        : "r"(a[0]), "r"(a[1]), "r"(a[2]), "r"(a[3]), "r"(b0), "r"(b1));
}
__device__ __forceinline__ void split_bf16(float v, bf16& h, bf16& l) {
    h = __float2bfloat16(v);
    l = __float2bfloat16(v - __bfloat162float(h));
}

#define TROW 80

// ======================= small kernels =======================
__global__ void embed_kernel(const int* __restrict__ x,
                             const float* __restrict__ bpe,
                             const float* __restrict__ pe,
                             bf16* __restrict__ ah, bf16* __restrict__ al) {
    int idx = blockIdx.x * blockDim.x + threadIdx.x;
    if (idx >= BB*SS*DD) return;
    int d  = idx % DD;
    int bs = idx / DD;
    int s  = bs % SS;
    int tok = x[bs];
    float v = bpe[(long)tok*DD + d] + pe[s*DD + d];
    g_h[idx] = v;
    bf16 h, l; split_bf16(v, h, l);
    ah[idx] = h; al[idx] = l;
}

__global__ void concat_bias(const float* __restrict__ bq, const float* __restrict__ bk,
                            const float* __restrict__ bv) {
    int idx = blockIdx.x * blockDim.x + threadIdx.x;
    if (idx >= LL*3*DD) return;
    int l = idx / (3*DD), n = idx % (3*DD);
    float v;
    if (n < DD)          v = bq[l*DD + n];
    else if (n < 2*DD)   v = bk[l*DD + n - DD];
    else                 v = bv[l*DD + n - 2*DD];
    g_bqkv[idx] = v;
}

// transpose + split v2: src fp32 [R][C] -> dst bf16 [C][R] hi/lo.
// 32x32 tile, 256 threads (32,8). Store phase: 4 rows/thread, 8-byte packed stores.
__global__ void conv_transpose(const float* __restrict__ src, bf16* __restrict__ dhi,
                               bf16* __restrict__ dlo, int R, int C,
                               long srcZ, int Z2, long dstZ1, long dstZ2) {
    __shared__ float t[32][36];    // [col][row], pad 36 for aligned float4 reads
    int c0 = blockIdx.x * 32, r0 = blockIdx.y * 32;
    long zs = (long)blockIdx.z * srcZ;
    long zd = (long)(blockIdx.z / Z2) * dstZ1 + (long)(blockIdx.z % Z2) * dstZ2;
    int tx = threadIdx.x, ty = threadIdx.y;   // (32, 8)

    #pragma unroll
    for (int i = 0; i < 4; i++) {
        int row = ty + i * 8;
        t[tx][row] = src[zs + (long)(r0 + row) * C + c0 + tx];
    }
    __syncthreads();

    // thread -> (col, 4-row chunk): cc = ty + (tx>>3)*8, r4 = (tx&7)*4
    int cc = ty + (tx >> 3) * 8;
    int r4 = (tx & 7) * 4;
    float4 v = *reinterpret_cast<const float4*>(&t[cc][r4]);
    bf16 h0,l0,h1,l1,h2,l2,h3,l3;
    split_bf16(v.x, h0, l0); split_bf16(v.y, h1, l1);
    split_bf16(v.z, h2, l2); split_bf16(v.w, h3, l3);
    long o = zd + (long)(c0 + cc) * R + r0 + r4;
    __nv_bfloat162 hv0(h0, h1), hv1(h2, h3), lv0(l0, l1), lv1(l2, l3);
    uint2 hp, lp;
    hp.x = *reinterpret_cast<uint32_t*>(&hv0); hp.y = *reinterpret_cast<uint32_t*>(&hv1);
    lp.x = *reinterpret_cast<uint32_t*>(&lv0); lp.y = *reinterpret_cast<uint32_t*>(&lv1);
    *reinterpret_cast<uint2*>(&dhi[o]) = hp;
    *reinterpret_cast<uint2*>(&dlo[o]) = lp;
}

// ======================= HMMA split-bf16 GEMM (round-5 proven config) =======================
// OUT: 0 = fp32 C row-major; 1 = bf16 hi/lo pair; 2 = QKV scatter to [which][b][h][s][e]
template<int TM>
__device__ __forceinline__ void load_chunk(
    uint32_t base, const bf16* __restrict__ Ah, const bf16* __restrict__ Al,
    const bf16* __restrict__ Bh, const bf16* __restrict__ Bl,
    int m0, int n0, int N, int K, int c, int tid)
{
    const uint32_t A_BYTES = TM * TROW;
    const uint32_t BUF = (2 * TM + 256) * TROW;
    uint32_t bb = base + (uint32_t)(c & 1) * BUF;
    int k0 = c << 5;
    #pragma unroll
    for (int i = 0; i < TM/64; i++) {
        int ci  = tid + i * 256;
        int row = ci >> 2, kq = ci & 3;
        uint32_t doff = (uint32_t)(row * TROW + kq * 16);
        long aoff = (long)(m0 + row) * K + k0 + kq * 8;
        cp16(bb + doff, Ah + aoff);
        cp16(bb + A_BYTES + doff, Al + aoff);
    }
    #pragma unroll
    for (int i = 0; i < 2; i++) {
        int ci  = tid + i * 256;
        int row = ci >> 2, kq = ci & 3;
        uint32_t doff = (uint32_t)(row * TROW + kq * 16);
        int nr = n0 + row;
        if (nr < N) {
            long boff = (long)nr * K + k0 + kq * 8;
            cp16(bb + 2*A_BYTES + doff, Bh + boff);
            cp16(bb + 2*A_BYTES + 128*TROW + doff, Bl + boff);
        } else {
            zero16(bb + 2*A_BYTES + doff);
            zero16(bb + 2*A_BYTES + 128*TROW + doff);
        }
    }
}

__device__ __forceinline__ long qkv_addr(int row, int col) {
    // row = b*SS + s ; col = which*768 + h*64 + e
    int b = row >> 7, s = row & (SS - 1);
    int which = col / DD;
    int rem = col - which * DD;
    int h = rem >> 6, e = rem & 63;
    return (long)which * QKV_PLANE + (((long)(b * HH + h) * SS + s) * HD) + e;
}

template<int MI, int OUT>
__global__ __launch_bounds__(256, 2) void gemm_hmma(
    const bf16* __restrict__ Ah, const bf16* __restrict__ Al,
    const bf16* __restrict__ Bh, const bf16* __restrict__ Bl,
    const float* __restrict__ bias, float* __restrict__ C,
    bf16* __restrict__ Oh, bf16* __restrict__ Ol,
    int N, int K)
{
    constexpr int TM = MI * 32;
    const uint32_t A_BYTES = TM * TROW;
    const uint32_t BUF = (2 * TM + 256) * TROW;
    extern __shared__ char smem[];
    const uint32_t base = smem_u32(smem);
    const int tid  = threadIdx.x;
    const int lane = tid & 31;
    const int w    = tid >> 5;
    const int wm   = w & 1;
    const int wn   = w >> 1;
    const int m0 = blockIdx.x * TM, n0 = blockIdx.y * 128;
    const int nCh = K >> 5;

    float acc[MI][4][4];
    #pragma unroll
    for (int i = 0; i < MI; i++)
        #pragma unroll
        for (int j = 0; j < 4; j++)
            #pragma unroll
            for (int q = 0; q < 4; q++) acc[i][j][q] = 0.f;

    const uint32_t a_loff = (uint32_t)((lane & 15) * TROW + ((lane >> 4) << 3) * 2);
    const uint32_t b_loff = (uint32_t)((((lane & 7) + ((lane & 16) ? 8 : 0)) * TROW) +
                                       ((lane & 8) ? 16 : 0));

    load_chunk<TM>(base, Ah, Al, Bh, Bl, m0, n0, N, K, 0, tid);
    cp_commit();

    for (int c = 0; c < nCh; c++) {
        if (c + 1 < nCh) {
            load_chunk<TM>(base, Ah, Al, Bh, Bl, m0, n0, N, K, c + 1, tid);
            cp_commit();
            asm volatile("cp.async.wait_group 1;" ::: "memory");
        } else {
            asm volatile("cp.async.wait_group 0;" ::: "memory");
        }
        __syncthreads();

        uint32_t bb = base + (uint32_t)(c & 1) * BUF;
        uint32_t aH = bb + (uint32_t)(wm * (MI * 16)) * TROW;
        uint32_t aL = aH + A_BYTES;
        uint32_t bH = bb + 2 * A_BYTES + (uint32_t)(wn * 32) * TROW;
        uint32_t bL = bH + 128 * TROW;

        #pragma unroll
        for (int ks = 0; ks < 2; ks++) {
            const uint32_t koff = (uint32_t)(ks * 32);
            uint32_t bh[2][4], bl[2][4];
            #pragma unroll
            for (int g = 0; g < 2; g++) {
                ldm4(bH + (uint32_t)(g * 16) * TROW + b_loff + koff, bh[g]);
                ldm4(bL + (uint32_t)(g * 16) * TROW + b_loff + koff, bl[g]);
            }
            #pragma unroll
            for (int mi = 0; mi < MI; mi++) {
                uint32_t ah[4], al[4];
                ldm4(aH + (uint32_t)(mi * 16) * TROW + a_loff + koff, ah);
                ldm4(aL + (uint32_t)(mi * 16) * TROW + a_loff + koff, al);
                #pragma unroll
                for (int ni = 0; ni < 4; ni++) {
                    const int g = ni >> 1, o = (ni & 1) * 2;
                    mma16816(acc[mi][ni], ah, bh[g][o], bh[g][o + 1]);
                    mma16816(acc[mi][ni], ah, bl[g][o], bl[g][o + 1]);
                    mma16816(acc[mi][ni], al, bh[g][o], bh[g][o + 1]);
                }
            }
        }
        __syncthreads();
    }

    // epilogue
    #pragma unroll
    for (int mi = 0; mi < MI; mi++) {
        int row = m0 + wm * (MI * 16) + mi * 16 + (lane >> 2);
        #pragma unroll
        for (int ni = 0; ni < 4; ni++) {
            int col = n0 + wn * 32 + ni * 8 + ((lane & 3) << 1);
            if (col < N) {
                float bx = bias[col], by = bias[col + 1];
                float v00 = acc[mi][ni][0] + bx, v01 = acc[mi][ni][1] + by;
                float v10 = acc[mi][ni][2] + bx, v11 = acc[mi][ni][3] + by;
                if (OUT == 0) {
                    *reinterpret_cast<float2*>(C + (long)row * N + col)       = make_float2(v00, v01);
                    *reinterpret_cast<float2*>(C + (long)(row + 8) * N + col) = make_float2(v10, v11);
                } else if (OUT == 2) {
                    long a0 = qkv_addr(row, col);
                    *reinterpret_cast<float2*>(C + a0)          = make_float2(v00, v01);
                    *reinterpret_cast<float2*>(C + a0 + 8 * HD) = make_float2(v10, v11);
                } else {
                    bf16 h0,l0,h1,l1,h2,l2,h3,l3;
                    split_bf16(v00, h0, l0); split_bf16(v01, h1, l1);
                    split_bf16(v10, h2, l2); split_bf16(v11, h3, l3);
                    *reinterpret_cast<__nv_bfloat162*>(Oh + (long)row * N + col)       = __nv_bfloat162(h0, h1);
                    *reinterpret_cast<__nv_bfloat162*>(Ol + (long)row * N + col)       = __nv_bfloat162(l0, l1);
                    *reinterpret_cast<__nv_bfloat162*>(Oh + (long)(row + 8) * N + col) = __nv_bfloat162(h2, h3);
                    *reinterpret_cast<__nv_bfloat162*>(Ol + (long)(row + 8) * N + col) = __nv_bfloat162(l2, l3);
                }
            }
        }
    }
}

// ======================= attention v3: per-query block, head-contiguous KV =======================
__global__ __launch_bounds__(128) void attn_kernel3(const int* __restrict__ ignore,
                                                    bf16* __restrict__ oh,
                                                    bf16* __restrict__ ol) {
    const int qi = blockIdx.x & (SS - 1);
    const int h  = (blockIdx.x >> 7) % HH;
    const int b  = blockIdx.x / (SS * HH);
    const int t  = threadIdx.x;

    __shared__ float qrow[HD];
    __shared__ float p[SS];
    __shared__ float red[SS];

    const long headoff = (long)(b * HH + h) * SS * HD;
    const float* Q = g_qkv + 0L * QKV_PLANE + headoff;
    const float* K = g_qkv + 1L * QKV_PLANE + headoff;
    const float* V = g_qkv + 2L * QKV_PLANE + headoff;

    if (t < HD) qrow[t] = Q[(long)qi * HD + t];
    __syncthreads();

    const bool allowed = (t <= qi) && (ignore[b * SS + t] == 0 || t == qi);
    float score = -INFINITY;
    if (allowed) {
        const float* kptr = K + (long)t * HD;
        float s = 0.f;
        #pragma unroll
        for (int e = 0; e < HD; e += 4) {
            float4 kv = *reinterpret_cast<const float4*>(kptr + e);
            s += qrow[e]*kv.x + qrow[e+1]*kv.y + qrow[e+2]*kv.z + qrow[e+3]*kv.w;
        }
        score = s * 0.125f;
    }
    red[t] = score; __syncthreads();
    for (int off = 64; off > 0; off >>= 1) {
        if (t < off) red[t] = fmaxf(red[t], red[t + off]);
        __syncthreads();
    }
    const float mx = red[0];
    __syncthreads();
    const float e = allowed ? expf(score - mx) : 0.f;
    p[t] = e; red[t] = e; __syncthreads();
    for (int off = 64; off > 0; off >>= 1) {
        if (t < off) red[t] += red[t + off];
        __syncthreads();
    }
    const float inv = 1.f / red[0];
    if (t < HD) {
        const float* vbase = V + t;
        float o = 0.f;
        #pragma unroll 8
        for (int k = 0; k <= qi; k++) o += p[k] * vbase[(long)k * HD];
        o *= inv;
        long oidx = (long)(b * SS + qi) * DD + h * HD + t;
        bf16 hh, ll; split_bf16(o, hh, ll);
        oh[oidx] = hh; ol[oidx] = ll;
    }
}

// ======================= residual (+GELU) + LayerNorm + split, single-pass =======================
__global__ __launch_bounds__(256) void add_ln_kernel(
    const float* __restrict__ res_in,
    const float* __restrict__ w, const float* __restrict__ bvec,
    bf16* __restrict__ ah, bf16* __restrict__ al,
    int dogelu) {
    const int row = blockIdx.x;
    const int t = threadIdx.x;
    __shared__ float rs1[8], rs2[8];

    float vals[3];
    float s1 = 0.f, s2 = 0.f;
    #pragma unroll
    for (int i = 0; i < 3; i++) {
        int d = t + i * 256;
        float r = res_in[(long)row * DD + d];
        if (dogelu) r = 0.5f * r * (1.f + erff(r * 0.70710678118f));
        float v = g_h[(long)row * DD + d] + r;
        vals[i] = v;
        s1 += v;
        s2 += v * v;
    }
    #pragma unroll
    for (int off = 16; off > 0; off >>= 1) {
        s1 += __shfl_xor_sync(0xffffffff, s1, off);
        s2 += __shfl_xor_sync(0xffffffff, s2, off);
    }
    if ((t & 31) == 0) { rs1[t >> 5] = s1; rs2[t >> 5] = s2; }
    __syncthreads();
    if (t < 32) {
        float a = (t < 8) ? rs1[t] : 0.f;
        float bq_ = (t < 8) ? rs2[t] : 0.f;
        #pragma unroll
        for (int off = 4; off > 0; off >>= 1) {
            a  += __shfl_xor_sync(0xffffffff, a, off);
            bq_ += __shfl_xor_sync(0xffffffff, bq_, off);
        }
        if (t == 0) { rs1[0] = a; rs2[0] = bq_; }
    }
    __syncthreads();
    const float mean = rs1[0] * (1.f / DD);
    const float var  = rs2[0] * (1.f / DD) - mean * mean;
    const float rstd = rsqrtf(var + 1e-5f);

    #pragma unroll
    for (int i = 0; i < 3; i++) {
        int d = t + i * 256;
        float v = (vals[i] - mean) * rstd * w[d] + bvec[d];
        g_h[(long)row * DD + d] = v;
        bf16 hh, ll; split_bf16(v, hh, ll);
        ah[(long)row * DD + d] = hh;
        al[(long)row * DD + d] = ll;
    }
}

// ======================= host orchestration =======================
extern "C" void kernel_launch(void* const* d_in, const int* in_sizes, int n_in,
                              void* d_out, int out_size) {
    const int*   x    = (const int*)  d_in[0];
    const int*   ign  = (const int*)  d_in[1];
    const float* bpe  = (const float*)d_in[2];
    const float* pe   = (const float*)d_in[3];
    const float* Wq   = (const float*)d_in[4];
    const float* bq   = (const float*)d_in[5];
    const float* Wk   = (const float*)d_in[6];
    const float* bk   = (const float*)d_in[7];
    const float* Wv   = (const float*)d_in[8];
    const float* bv   = (const float*)d_in[9];
    const float* Wo   = (const float*)d_in[10];
    const float* bo   = (const float*)d_in[11];
    const float* W1   = (const float*)d_in[12];
    const float* b1   = (const float*)d_in[13];
    const float* W2   = (const float*)d_in[14];
    const float* b2   = (const float*)d_in[15];
    const float* ln1w = (const float*)d_in[16];
    const float* ln1b = (const float*)d_in[17];
    const float* ln2w = (const float*)d_in[18];
    const float* ln2b = (const float*)d_in[19];
    const float* Wout = (const float*)d_in[20];
    const float* bout = (const float*)d_in[21];
    float* out = (float*)d_out;

    float *gh, *gqkv, *gproj, *gff2, *gbqkv;
    cudaGetSymbolAddress((void**)&gh,    g_h);
    cudaGetSymbolAddress((void**)&gqkv,  g_qkv);
    cudaGetSymbolAddress((void**)&gproj, g_proj);
    cudaGetSymbolAddress((void**)&gff2,  g_ff2);
    cudaGetSymbolAddress((void**)&gbqkv, g_bqkv);

    bf16 *wqkv_h, *wo_h, *w1_h, *w2_h, *wout_h, *actA_h, *actB_h;
    bf16 *wqkv_l, *wo_l, *w1_l, *w2_l, *wout_l, *actA_l, *actB_l;
    void* p;
    cudaGetSymbolAddress(&p, s_wqkv); wqkv_h = (bf16*)p; wqkv_l = wqkv_h + (long)LL*3*DD*DD;
    cudaGetSymbolAddress(&p, s_wo);   wo_h = (bf16*)p;   wo_l   = wo_h   + (long)LL*DD*DD;
    cudaGetSymbolAddress(&p, s_w1);   w1_h = (bf16*)p;   w1_l   = w1_h   + (long)LL*DD*FF;
    cudaGetSymbolAddress(&p, s_w2);   w2_h = (bf16*)p;   w2_l   = w2_h   + (long)LL*FF*DD;
    cudaGetSymbolAddress(&p, s_wout); wout_h = (bf16*)p; wout_l = wout_h + (long)VV*DD;
    cudaGetSymbolAddress(&p, s_actA); actA_h = (bf16*)p; actA_l = actA_h + (long)BB*SS*FF;
    cudaGetSymbolAddress(&p, s_actB); actB_h = (bf16*)p; actB_l = actB_h + (long)BB*SS*FF;

    const int SM128 = (2*128 + 256) * TROW * 2;   // 81920
    const int SM64  = (2*64  + 256) * TROW * 2;   // 61440
    cudaFuncSetAttribute(gemm_hmma<4,2>, cudaFuncAttributeMaxDynamicSharedMemorySize, SM128);
    cudaFuncSetAttribute(gemm_hmma<4,0>, cudaFuncAttributeMaxDynamicSharedMemorySize, SM128);
    cudaFuncSetAttribute(gemm_hmma<4,1>, cudaFuncAttributeMaxDynamicSharedMemorySize, SM128);
    cudaFuncSetAttribute(gemm_hmma<2,0>, cudaFuncAttributeMaxDynamicSharedMemorySize, SM64);

    const int M = BB * SS;  // 2048
    dim3 tb32(32, 8);

    // ---- launches 0-4: qkv weight convs, embed, concat (ncu profiles launch #5 = first GEMM) ----
    conv_transpose<<<dim3(HD/32, DD/32, LL*HH), tb32>>>(Wq, wqkv_h + 0L*DD*DD, wqkv_l + 0L*DD*DD,
        DD, HD, (long)DD*HD, HH, (long)3*DD*DD, (long)HD*DD);
    conv_transpose<<<dim3(HD/32, DD/32, LL*HH), tb32>>>(Wk, wqkv_h + 1L*DD*DD, wqkv_l + 1L*DD*DD,
        DD, HD, (long)DD*HD, HH, (long)3*DD*DD, (long)HD*DD);
    conv_transpose<<<dim3(HD/32, DD/32, LL*HH), tb32>>>(Wv, wqkv_h + 2L*DD*DD, wqkv_l + 2L*DD*DD,
        DD, HD, (long)DD*HD, HH, (long)3*DD*DD, (long)HD*DD);
    embed_kernel<<<(BB*SS*DD + 255)/256, 256>>>(x, bpe, pe, actA_h, actA_l);
    concat_bias<<<(LL*3*DD + 255)/256, 256>>>(bq, bk, bv);

    // ---- launch 5: first QKV GEMM (profiled by ncu -s 5 -c 1) ----
    gemm_hmma<4,2><<<dim3(M/128, (3*DD)/128), 256, SM128>>>(actA_h, actA_l,
        wqkv_h, wqkv_l, gbqkv, gqkv, nullptr, nullptr, 3*DD, DD);

    // ---- remaining weight conversions (complete before first use below) ----
    conv_transpose<<<dim3(DD/32, DD/32, LL), tb32>>>(Wo, wo_h, wo_l,
        DD, DD, (long)DD*DD, 1, (long)DD*DD, 0);
    conv_transpose<<<dim3(FF/32, DD/32, LL), tb32>>>(W1, w1_h, w1_l,
        DD, FF, (long)DD*FF, 1, (long)DD*FF, 0);
    conv_transpose<<<dim3(DD/32, FF/32, LL), tb32>>>(W2, w2_h, w2_l,
        FF, DD, (long)FF*DD, 1, (long)FF*DD, 0);
    conv_transpose<<<dim3(VV/32, DD/32, 1), tb32>>>(Wout, wout_h, wout_l,
        DD, VV, 0, 1, 0, 0);

    for (int l = 0; l < LL; l++) {
        if (l > 0) {
            gemm_hmma<4,2><<<dim3(M/128, (3*DD)/128), 256, SM128>>>(actA_h, actA_l,
                wqkv_h + (long)l*3*DD*DD, wqkv_l + (long)l*3*DD*DD,
                gbqkv + (long)l*3*DD, gqkv, nullptr, nullptr, 3*DD, DD);
        }

        attn_kernel3<<<BB*HH*SS, 128>>>(ign, actB_h, actB_l);

        gemm_hmma<2,0><<<dim3(M/64, DD/128), 256, SM64>>>(actB_h, actB_l,
            wo_h + (long)l*DD*DD, wo_l + (long)l*DD*DD,
            bo + (long)l*DD, gproj, nullptr, nullptr, DD, DD);
        add_ln_kernel<<<M, 256>>>(gproj, ln1w + (long)l*DD, ln1b + (long)l*DD,
                                  actA_h, actA_l, 0);

        gemm_hmma<4,1><<<dim3(M/128, FF/128), 256, SM128>>>(actA_h, actA_l,
            w1_h + (long)l*DD*FF, w1_l + (long)l*DD*FF,
            b1 + (long)l*FF, nullptr, actB_h, actB_l, FF, DD);
        gemm_hmma<2,0><<<dim3(M/64, DD/128), 256, SM64>>>(actB_h, actB_l,
            w2_h + (long)l*FF*DD, w2_l + (long)l*FF*DD,
            b2 + (long)l*DD, gff2, nullptr, nullptr, DD, FF);
        add_ln_kernel<<<M, 256>>>(gff2, ln2w + (long)l*DD, ln2b + (long)l*DD,
                                  actA_h, actA_l, 1);
    }

    gemm_hmma<4,0><<<dim3(M/128, (VV + 127)/128), 256, SM128>>>(actA_h, actA_l,
        wout_h, wout_l, bout, out, nullptr, nullptr, VV, DD);
}